// round 8
// baseline (speedup 1.0000x reference)
#include <cuda_runtime.h>
#include <cuda_bf16.h>
#include <math.h>
#include <stdint.h>
#include <stddef.h>

#define N_ENT 50000
#define N_TX  40000
#define D     128
#define F     432
#define T     11
#define CDIM  (F + T * D)      /* 1840 */
#define K1PAD 1856
#define QLD   512
#define EPS   1e-5f
#define SCALE 0.08838834764831845f

#define MPAD_E 50048           /* 391*128 */
#define MPAD_T 40064           /* 313*128 */

/* ------------------------------------------------------------------ */
__device__ float    g_qkvs[(size_t)T * N_ENT * QLD];   /* 1.13 GB */
__device__ float    g_S[(size_t)T * N_ENT * D];        /* 282 MB: agg, then hn in-place */
__device__ float    g_denom[(size_t)T * N_ENT];
__device__ float    g_comb[(size_t)MPAD_T * CDIM];
__device__ float    g_x1[(size_t)N_TX * D];
__device__ float    g_x2[(size_t)N_TX * 64];
__device__ float    g_Bcat[D * QLD];
__device__ float    g_bcat[QLD];
__device__ __nv_bfloat16 g_Ah[(size_t)T * MPAD_E * D], g_Al[(size_t)T * MPAD_E * D];
__device__ __nv_bfloat16 g_Bh[D * QLD],    g_Bl[D * QLD];
__device__ __nv_bfloat16 g_W1h[K1PAD * D], g_W1l[K1PAD * D];
__device__ __nv_bfloat16 g_W2h[D * 64],    g_W2l[D * 64];

/* ------------------------------------------------------------------ */
__global__ void pack_w(const float* __restrict__ Wq, const float* __restrict__ Wk,
                       const float* __restrict__ Wv, const float* __restrict__ Ws,
                       const float* __restrict__ bq, const float* __restrict__ bk,
                       const float* __restrict__ bv, const float* __restrict__ bs,
                       float* __restrict__ Bcat, float* __restrict__ bcat) {
    int i = blockIdx.x * blockDim.x + threadIdx.x;
    if (i >= D * QLD) return;
    int n = i & (QLD - 1);
    int k = i >> 9;
    const float* W = (n < 128) ? Wq : (n < 256) ? Wk : (n < 384) ? Wv : Ws;
    int nn = n & 127;
    Bcat[k * QLD + n] = W[k * 128 + nn];
    if (k == 0) {
        const float* bb = (n < 128) ? bq : (n < 256) ? bk : (n < 384) ? bv : bs;
        bcat[n] = bb[nn];
    }
}

__global__ void split_w(const float* __restrict__ src,
                        __nv_bfloat16* __restrict__ dh, __nv_bfloat16* __restrict__ dl,
                        int Kreal, int Kpad, int Ncols) {
    int i = blockIdx.x * blockDim.x + threadIdx.x;
    if (i >= Kpad * Ncols) return;
    int k = i / Ncols;
    float v = (k < Kreal) ? src[i] : 0.f;
    __nv_bfloat16 h = __float2bfloat16_rn(v);
    __nv_bfloat16 l = __float2bfloat16_rn(v - __bfloat162float(h));
    dh[i] = h;
    dl[i] = l;
}

__global__ void gather_split_all(const float* __restrict__ emb, const int* __restrict__ ent_x,
                                 __nv_bfloat16* __restrict__ Ah, __nv_bfloat16* __restrict__ Al) {
    long long i = (long long)blockIdx.x * blockDim.x + threadIdx.x;
    const long long TOT = (long long)T * N_ENT * (D / 4);
    if (i >= TOT) return;
    int c4  = (int)(i & 31);
    long long rowg = i >> 5;
    int t   = (int)(rowg / N_ENT);
    int row = (int)(rowg - (long long)t * N_ENT);
    int r = ent_x[rowg];
    float4 v = ((const float4*)(emb + ((size_t)t * N_ENT + r) * D))[c4];
    float vv[4] = { v.x, v.y, v.z, v.w };
    __nv_bfloat16 h[4], l[4];
#pragma unroll
    for (int j = 0; j < 4; j++) {
        h[j] = __float2bfloat16_rn(vv[j]);
        l[j] = __float2bfloat16_rn(vv[j] - __bfloat162float(h[j]));
    }
    size_t o = ((size_t)t * MPAD_E + row) * D + (c4 << 2);
    *(uint2*)(Ah + o) = *(uint2*)h;
    *(uint2*)(Al + o) = *(uint2*)l;
}

__global__ void comb_init(const float* __restrict__ tx, float* __restrict__ comb) {
    int i = blockIdx.x * blockDim.x + threadIdx.x;
    const int TOT = N_TX * (CDIM / 4);
    if (i >= TOT) return;
    int row = i / (CDIM / 4);
    int c4  = i - row * (CDIM / 4);
    float4 v = make_float4(0.f, 0.f, 0.f, 0.f);
    if (c4 < F / 4) v = ((const float4*)(tx + (size_t)row * F))[c4];
    ((float4*)(comb + (size_t)row * CDIM))[c4] = v;
}

__global__ void zero_sd(float* __restrict__ S, float* __restrict__ denom) {
    long long i = (long long)blockIdx.x * blockDim.x + threadIdx.x;
    const long long S4 = (long long)T * N_ENT * D / 4;
    if (i < S4) ((float4*)S)[i] = make_float4(0.f, 0.f, 0.f, 0.f);
    if (i < (long long)T * N_ENT) denom[i] = 0.f;
}

/* ------------------------------------------------------------------ */
__device__ __forceinline__ void ldsm4(uint32_t* r, const void* p) {
    uint32_t a = (uint32_t)__cvta_generic_to_shared(p);
    asm volatile("ldmatrix.sync.aligned.m8n8.x4.shared.b16 {%0,%1,%2,%3}, [%4];"
                 : "=r"(r[0]), "=r"(r[1]), "=r"(r[2]), "=r"(r[3]) : "r"(a));
}
__device__ __forceinline__ void ldsm4t(uint32_t* r, const void* p) {
    uint32_t a = (uint32_t)__cvta_generic_to_shared(p);
    asm volatile("ldmatrix.sync.aligned.m8n8.x4.trans.shared.b16 {%0,%1,%2,%3}, [%4];"
                 : "=r"(r[0]), "=r"(r[1]), "=r"(r[2]), "=r"(r[3]) : "r"(a));
}
__device__ __forceinline__ void mma16816(float* c, const uint32_t* a, const uint32_t* b) {
    asm volatile(
        "mma.sync.aligned.m16n8k16.row.col.f32.bf16.bf16.f32 "
        "{%0,%1,%2,%3}, {%4,%5,%6,%7}, {%8,%9}, {%0,%1,%2,%3};\n"
        : "+f"(c[0]), "+f"(c[1]), "+f"(c[2]), "+f"(c[3])
        : "r"(a[0]), "r"(a[1]), "r"(a[2]), "r"(a[3]), "r"(b[0]), "r"(b[1]));
}

/* ------------------------------------------------------------------ */
#define ASTR  40
#define BSTR2 144

template<int SPLITA>
__global__ void __launch_bounds__(256) gemm128(
    const float* __restrict__ Afp,
    const __nv_bfloat16* __restrict__ Ahg, const __nv_bfloat16* __restrict__ Alg,
    const __nv_bfloat16* __restrict__ Bhg, const __nv_bfloat16* __restrict__ Blg,
    const float* __restrict__ bias, float* __restrict__ C,
    int M, int N, int Kreal, int Kpad, int relu,
    long long strideA, long long strideC)
{
    __shared__ __nv_bfloat16 Ahs[128][ASTR];
    __shared__ __nv_bfloat16 Als[128][ASTR];
    __shared__ __nv_bfloat16 Bhs[32][BSTR2];
    __shared__ __nv_bfloat16 Bls[32][BSTR2];

    const int tid  = threadIdx.x;
    const int lane = tid & 31;
    const int warp = tid >> 5;
    const int wm   = warp >> 1;
    const int wn   = warp & 1;
    const int m0   = blockIdx.y * 128;
    const int n0   = blockIdx.x * 128;
    const long long zA = (long long)blockIdx.z * strideA;
    const long long zC = (long long)blockIdx.z * strideC;

    const int arow  = tid >> 1;
    const int acolg = (tid & 1) << 4;
    const int brow  = tid >> 3;
    const int bcol  = (tid & 7) << 4;

    float acc[2][8][4];
#pragma unroll
    for (int a = 0; a < 2; a++)
#pragma unroll
        for (int b = 0; b < 8; b++)
#pragma unroll
            for (int c = 0; c < 4; c++) acc[a][b][c] = 0.f;

    uint4  sAh[2], sAl[2];
    float4 sAf[4];
    uint4  sBh[2], sBl[2];

#define LOADT(K0)                                                              \
    do {                                                                       \
        if (SPLITA) {                                                          \
            size_t ao = (size_t)(zA + (long long)(m0 + arow) * Kreal           \
                                 + (K0) + acolg);                              \
            sAh[0] = *(const uint4*)(Ahg + ao);                                \
            sAh[1] = *(const uint4*)(Ahg + ao + 8);                            \
            sAl[0] = *(const uint4*)(Alg + ao);                                \
            sAl[1] = *(const uint4*)(Alg + ao + 8);                            \
        } else {                                                               \
            if ((K0) + acolg < Kreal) {                                        \
                const float4* p = (const float4*)(Afp +                        \
                    (size_t)(m0 + arow) * Kreal + (K0) + acolg);               \
                sAf[0] = p[0]; sAf[1] = p[1]; sAf[2] = p[2]; sAf[3] = p[3];    \
            } else {                                                           \
                sAf[0] = sAf[1] = sAf[2] = sAf[3] =                            \
                    make_float4(0.f, 0.f, 0.f, 0.f);                           \
            }                                                                  \
        }                                                                      \
        size_t bo = (size_t)((K0) + brow) * N + n0 + bcol;                     \
        sBh[0] = *(const uint4*)(Bhg + bo);                                    \
        sBh[1] = *(const uint4*)(Bhg + bo + 8);                                \
        sBl[0] = *(const uint4*)(Blg + bo);                                    \
        sBl[1] = *(const uint4*)(Blg + bo + 8);                                \
    } while (0)

    LOADT(0);

    for (int k0 = 0; k0 < Kpad; k0 += 32) {
        if (SPLITA) {
            *(uint4*)&Ahs[arow][acolg]     = sAh[0];
            *(uint4*)&Ahs[arow][acolg + 8] = sAh[1];
            *(uint4*)&Als[arow][acolg]     = sAl[0];
            *(uint4*)&Als[arow][acolg + 8] = sAl[1];
        } else {
            const float* fv = (const float*)sAf;
#pragma unroll
            for (int j = 0; j < 8; j++) {
                float x0 = fv[2 * j], x1 = fv[2 * j + 1];
                __nv_bfloat16 h0 = __float2bfloat16_rn(x0);
                __nv_bfloat16 l0 = __float2bfloat16_rn(x0 - __bfloat162float(h0));
                __nv_bfloat16 h1 = __float2bfloat16_rn(x1);
                __nv_bfloat16 l1 = __float2bfloat16_rn(x1 - __bfloat162float(h1));
                __nv_bfloat162 hp; hp.x = h0; hp.y = h1;
                __nv_bfloat162 lp; lp.x = l0; lp.y = l1;
                *(__nv_bfloat162*)&Ahs[arow][acolg + 2 * j] = hp;
                *(__nv_bfloat162*)&Als[arow][acolg + 2 * j] = lp;
            }
        }
        *(uint4*)&Bhs[brow][bcol]     = sBh[0];
        *(uint4*)&Bhs[brow][bcol + 8] = sBh[1];
        *(uint4*)&Bls[brow][bcol]     = sBl[0];
        *(uint4*)&Bls[brow][bcol + 8] = sBl[1];
        __syncthreads();

        int kn = k0 + 32;
        if (kn < Kpad) LOADT(kn);

#pragma unroll
        for (int ks = 0; ks < 2; ks++) {
            const int kk = ks << 4;
            uint32_t afh[2][4], afl[2][4];
#pragma unroll
            for (int mt = 0; mt < 2; mt++) {
                const int r = wm * 32 + mt * 16 + (lane & 15);
                const int c = kk + ((lane >> 4) << 3);
                ldsm4(afh[mt], &Ahs[r][c]);
                ldsm4(afl[mt], &Als[r][c]);
            }
            uint32_t bfh[4][4], bfl[4][4];
#pragma unroll
            for (int nc = 0; nc < 4; nc++) {
                const int r = kk + (lane & 15);
                const int c = wn * 64 + nc * 16 + ((lane >> 4) << 3);
                ldsm4t(bfh[nc], &Bhs[r][c]);
                ldsm4t(bfl[nc], &Bls[r][c]);
            }
#pragma unroll
            for (int mt = 0; mt < 2; mt++)
#pragma unroll
                for (int nt = 0; nt < 8; nt++) {
                    const int nc = nt >> 1, p = (nt & 1) << 1;
                    uint32_t bh2[2] = { bfh[nc][p], bfh[nc][p + 1] };
                    uint32_t bl2[2] = { bfl[nc][p], bfl[nc][p + 1] };
                    mma16816(acc[mt][nt], afh[mt], bh2);
                    mma16816(acc[mt][nt], afl[mt], bh2);
                    mma16816(acc[mt][nt], afh[mt], bl2);
                }
        }
        __syncthreads();
    }
#undef LOADT

#pragma unroll
    for (int mt = 0; mt < 2; mt++)
#pragma unroll
        for (int nt = 0; nt < 8; nt++) {
            const int col = n0 + wn * 64 + nt * 8 + ((lane & 3) << 1);
            const float bx = bias[col], by = bias[col + 1];
            const int r0 = m0 + wm * 32 + mt * 16 + (lane >> 2);
            float o0 = acc[mt][nt][0] + bx, o1 = acc[mt][nt][1] + by;
            float o2 = acc[mt][nt][2] + bx, o3 = acc[mt][nt][3] + by;
            if (relu) {
                o0 = fmaxf(o0, 0.f); o1 = fmaxf(o1, 0.f);
                o2 = fmaxf(o2, 0.f); o3 = fmaxf(o3, 0.f);
            }
            if (r0 < M)     { float2 v = make_float2(o0, o1);
                              *(float2*)(C + zC + (size_t)r0 * N + col) = v; }
            if (r0 + 8 < M) { float2 v = make_float2(o2, o3);
                              *(float2*)(C + zC + (size_t)(r0 + 8) * N + col) = v; }
        }
}

/* ------------------------------------------------------------------ */
#define BSTR 72
__global__ void __launch_bounds__(256) gemm_bf16x2(
    const float* __restrict__ A,
    const __nv_bfloat16* __restrict__ Bhg, const __nv_bfloat16* __restrict__ Blg,
    const float* __restrict__ bias, float* __restrict__ C,
    int M, int N, int Kreal, int Kpad, int relu)
{
    __shared__ __nv_bfloat16 Ah[128][ASTR];
    __shared__ __nv_bfloat16 Al[128][ASTR];
    __shared__ __nv_bfloat16 Bhs[32][BSTR];
    __shared__ __nv_bfloat16 Bls[32][BSTR];

    const int tid  = threadIdx.x;
    const int lane = tid & 31;
    const int warp = tid >> 5;
    const int wm   = warp >> 1;
    const int wn   = warp & 1;
    const int m0   = blockIdx.y * 128;
    const int n0   = blockIdx.x * 64;

    const int arow  = tid >> 1;
    const int acolg = (tid & 1) << 4;
    const float* aptr = NULL;
    {
        int gm = m0 + arow;
        if (gm < M) aptr = A + (size_t)gm * Kreal;
    }
    const int brow  = tid >> 3;
    const int bcolg = (tid & 7) << 3;

    float acc[2][4][4];
#pragma unroll
    for (int i = 0; i < 2; i++)
#pragma unroll
        for (int j = 0; j < 4; j++)
#pragma unroll
            for (int l = 0; l < 4; l++) acc[i][j][l] = 0.f;

    for (int k0 = 0; k0 < Kpad; k0 += 32) {
        float4 f[4];
        if (aptr && (k0 + acolg) < Kreal) {
            const float4* p = (const float4*)(aptr + k0 + acolg);
            f[0] = p[0]; f[1] = p[1]; f[2] = p[2]; f[3] = p[3];
        } else {
            f[0] = f[1] = f[2] = f[3] = make_float4(0.f, 0.f, 0.f, 0.f);
        }
        const float* fv = (const float*)f;
#pragma unroll
        for (int j = 0; j < 8; j++) {
            float x0 = fv[2 * j], x1 = fv[2 * j + 1];
            __nv_bfloat16 h0 = __float2bfloat16_rn(x0);
            __nv_bfloat16 l0 = __float2bfloat16_rn(x0 - __bfloat162float(h0));
            __nv_bfloat16 h1 = __float2bfloat16_rn(x1);
            __nv_bfloat16 l1 = __float2bfloat16_rn(x1 - __bfloat162float(h1));
            __nv_bfloat162 hp; hp.x = h0; hp.y = h1;
            __nv_bfloat162 lp; lp.x = l0; lp.y = l1;
            *(__nv_bfloat162*)&Ah[arow][acolg + 2 * j] = hp;
            *(__nv_bfloat162*)&Al[arow][acolg + 2 * j] = lp;
        }
        {
            size_t off = (size_t)(k0 + brow) * N + n0 + bcolg;
            uint4 vh = *(const uint4*)(Bhg + off);
            uint4 vl = *(const uint4*)(Blg + off);
            *(uint4*)&Bhs[brow][bcolg] = vh;
            *(uint4*)&Bls[brow][bcolg] = vl;
        }
        __syncthreads();

#pragma unroll
        for (int ks = 0; ks < 2; ks++) {
            const int kk = ks << 4;
            uint32_t afh[2][4], afl[2][4];
#pragma unroll
            for (int mt = 0; mt < 2; mt++) {
                const int r = wm * 32 + mt * 16 + (lane & 15);
                const int c = kk + ((lane >> 4) << 3);
                ldsm4(afh[mt], &Ah[r][c]);
                ldsm4(afl[mt], &Al[r][c]);
            }
            uint32_t bfh[2][4], bfl[2][4];
#pragma unroll
            for (int nc = 0; nc < 2; nc++) {
                const int r = kk + (lane & 15);
                const int c = wn * 32 + nc * 16 + ((lane >> 4) << 3);
                ldsm4t(bfh[nc], &Bhs[r][c]);
                ldsm4t(bfl[nc], &Bls[r][c]);
            }
#pragma unroll
            for (int mt = 0; mt < 2; mt++)
#pragma unroll
                for (int nt = 0; nt < 4; nt++) {
                    const int nc = nt >> 1, p = (nt & 1) << 1;
                    uint32_t bh2[2] = { bfh[nc][p], bfh[nc][p + 1] };
                    uint32_t bl2[2] = { bfl[nc][p], bfl[nc][p + 1] };
                    mma16816(acc[mt][nt], afh[mt], bh2);
                    mma16816(acc[mt][nt], afl[mt], bh2);
                    mma16816(acc[mt][nt], afh[mt], bl2);
                }
        }
        __syncthreads();
    }

#pragma unroll
    for (int mt = 0; mt < 2; mt++)
#pragma unroll
        for (int nt = 0; nt < 4; nt++) {
            const int col = n0 + wn * 32 + nt * 8 + ((lane & 3) << 1);
            const float bx = bias[col], by = bias[col + 1];
            const int r0 = m0 + wm * 32 + mt * 16 + (lane >> 2);
            float o0 = acc[mt][nt][0] + bx, o1 = acc[mt][nt][1] + by;
            float o2 = acc[mt][nt][2] + bx, o3 = acc[mt][nt][3] + by;
            if (relu) {
                o0 = fmaxf(o0, 0.f); o1 = fmaxf(o1, 0.f);
                o2 = fmaxf(o2, 0.f); o3 = fmaxf(o3, 0.f);
            }
            if (r0 < M)     { float2 v = make_float2(o0, o1); *(float2*)(C + (size_t)r0 * N + col) = v; }
            if (r0 + 8 < M) { float2 v = make_float2(o2, o3); *(float2*)(C + (size_t)(r0 + 8) * N + col) = v; }
        }
}

/* ------------------------------------------------------------------ */
/* Edge pass (all types): ex = exp(dot(q[dst],k[src])*scale);          */
/* denom[dst] += ex;  S[dst] += ex * v[src]                            */
/* ------------------------------------------------------------------ */
__global__ void edge_fused_all(const float* __restrict__ qkvs,
                               const int* __restrict__ e_src, const int* __restrict__ e_dst,
                               float* __restrict__ S, float* __restrict__ denom) {
    long long w = ((long long)blockIdx.x * blockDim.x + threadIdx.x) >> 5;
    int lane = threadIdx.x & 31;
    if (w >= (long long)T * N_TX) return;
    int t = (int)(w / N_TX);
    int e = (int)(w - (long long)t * N_TX);
    int dd = e_dst[(size_t)t * N_TX + e];
    int ss = e_src[(size_t)t * N_TX + e];
    const float* qk = qkvs + (size_t)t * N_ENT * QLD;
    float4 qv = ((const float4*)(qk + (size_t)dd * QLD))[lane];
    float4 kv = ((const float4*)(qk + (size_t)ss * QLD + 128))[lane];
    float acc = qv.x * kv.x + qv.y * kv.y + qv.z * kv.z + qv.w * kv.w;
#pragma unroll
    for (int o = 16; o; o >>= 1) acc += __shfl_xor_sync(0xFFFFFFFFu, acc, o);
    float exv = expf(acc * SCALE);   /* |score| << 1: no max-shift needed */
    float4 vv = ((const float4*)(qk + (size_t)ss * QLD + 256))[lane];
    float* so = S + ((size_t)t * N_ENT + dd) * D + (lane << 2);
    atomicAdd(so + 0, exv * vv.x);
    atomicAdd(so + 1, exv * vv.y);
    atomicAdd(so + 2, exv * vv.z);
    atomicAdd(so + 3, exv * vv.w);
    if (lane == 0) atomicAdd(&denom[(size_t)t * N_ENT + dd], exv);
}

/* ------------------------------------------------------------------ */
/* Per-node: out = skip + S/denom; LayerNorm; write back into S.       */
/* ------------------------------------------------------------------ */
__global__ void norm_ln_all(const float* __restrict__ qkvs,
                            float* __restrict__ S, const float* __restrict__ denom,
                            const float* __restrict__ ln_g, const float* __restrict__ ln_b) {
    long long w = ((long long)blockIdx.x * blockDim.x + threadIdx.x) >> 5;
    int lane = threadIdx.x & 31;
    if (w >= (long long)T * N_ENT) return;
    int t = (int)(w / N_ENT);
    long long node = w;               /* t*N_ENT + n */

    float4 skip = ((const float4*)(qkvs + (size_t)node * QLD + 384))[lane];
    float dn = denom[node];
    float inv = (dn > 0.f) ? (1.f / dn) : 0.f;
    float* srow = S + (size_t)node * D;
    float4 sv = ((const float4*)srow)[lane];
    float x0 = skip.x + sv.x * inv;
    float x1 = skip.y + sv.y * inv;
    float x2 = skip.z + sv.z * inv;
    float x3 = skip.w + sv.w * inv;

    float s = x0 + x1 + x2 + x3;
#pragma unroll
    for (int o = 16; o; o >>= 1) s += __shfl_xor_sync(0xFFFFFFFFu, s, o);
    float mu = s * (1.f / 128.f);
    float d0 = x0 - mu, d1 = x1 - mu, d2 = x2 - mu, d3 = x3 - mu;
    float v = d0 * d0 + d1 * d1 + d2 * d2 + d3 * d3;
#pragma unroll
    for (int o = 16; o; o >>= 1) v += __shfl_xor_sync(0xFFFFFFFFu, v, o);
    float rstd = rsqrtf(v * (1.f / 128.f) + EPS);

    float4 gg = ((const float4*)(ln_g + t * D))[lane];
    float4 bb = ((const float4*)(ln_b + t * D))[lane];
    float4 o4;
    o4.x = d0 * rstd * gg.x + bb.x;
    o4.y = d1 * rstd * gg.y + bb.y;
    o4.z = d2 * rstd * gg.z + bb.z;
    o4.w = d3 * rstd * gg.w + bb.w;
    ((float4*)srow)[lane] = o4;
}

/* per edge: comb[dst, F+t*D ..] += S(=hn)[src]                        */
__global__ void scatter_all(const float* __restrict__ S,
                            const int* __restrict__ e_src, const int* __restrict__ e_dst,
                            float* __restrict__ comb) {
    long long w = ((long long)blockIdx.x * blockDim.x + threadIdx.x) >> 5;
    int lane = threadIdx.x & 31;
    if (w >= (long long)T * N_TX) return;
    int t = (int)(w / N_TX);
    int e = (int)(w - (long long)t * N_TX);
    int ss = e_src[(size_t)t * N_TX + e];
    int dd = e_dst[(size_t)t * N_TX + e];
    float4 hv = ((const float4*)(S + ((size_t)t * N_ENT + ss) * D))[lane];
    float* c = comb + (size_t)dd * CDIM + F + t * D + (lane << 2);
    atomicAdd(c + 0, hv.x);
    atomicAdd(c + 1, hv.y);
    atomicAdd(c + 2, hv.z);
    atomicAdd(c + 3, hv.w);
}

__global__ void final_dot(const float* __restrict__ x2, const float* __restrict__ W3,
                          const float* __restrict__ b3, float* __restrict__ out) {
    int r = (blockIdx.x * blockDim.x + threadIdx.x) >> 5;
    int lane = threadIdx.x & 31;
    if (r >= N_TX) return;
    float2 xv = ((const float2*)(x2 + (size_t)r * 64))[lane];
    float2 wv = ((const float2*)W3)[lane];
    float s = xv.x * wv.x + xv.y * wv.y;
#pragma unroll
    for (int o = 16; o; o >>= 1) s += __shfl_xor_sync(0xFFFFFFFFu, s, o);
    if (lane == 0) out[r] = s + b3[0];
}

/* ------------------------------------------------------------------ */
extern "C" void kernel_launch(void* const* d_in, const int* in_sizes, int n_in,
                              void* d_out, int out_size) {
    const float* tx_x  = (const float*)d_in[0];
    const int*   ent_x = (const int*)d_in[1];
    const int*   e_src = (const int*)d_in[2];
    const int*   e_dst = (const int*)d_in[3];
    const float* emb   = (const float*)d_in[4];
    const float* ln_g  = (const float*)d_in[5];
    const float* ln_b  = (const float*)d_in[6];
    const float* Wq = (const float*)d_in[7];  const float* bq = (const float*)d_in[8];
    const float* Wk = (const float*)d_in[9];  const float* bk = (const float*)d_in[10];
    const float* Wv = (const float*)d_in[11]; const float* bv = (const float*)d_in[12];
    const float* Ws = (const float*)d_in[13]; const float* bs = (const float*)d_in[14];
    const float* W1 = (const float*)d_in[15]; const float* b1 = (const float*)d_in[16];
    const float* W2 = (const float*)d_in[17]; const float* b2 = (const float*)d_in[18];
    const float* W3 = (const float*)d_in[19]; const float* b3 = (const float*)d_in[20];
    float* out = (float*)d_out;

    float *qkvs, *S, *denom, *comb, *x1, *x2, *Bcat, *bcat;
    __nv_bfloat16 *Ah, *Al, *Bh, *Bl, *W1h, *W1l, *W2h, *W2l;
    cudaGetSymbolAddress((void**)&qkvs,  g_qkvs);
    cudaGetSymbolAddress((void**)&S,     g_S);
    cudaGetSymbolAddress((void**)&denom, g_denom);
    cudaGetSymbolAddress((void**)&comb,  g_comb);
    cudaGetSymbolAddress((void**)&x1,    g_x1);
    cudaGetSymbolAddress((void**)&x2,    g_x2);
    cudaGetSymbolAddress((void**)&Bcat,  g_Bcat);
    cudaGetSymbolAddress((void**)&bcat,  g_bcat);
    cudaGetSymbolAddress((void**)&Ah,    g_Ah);
    cudaGetSymbolAddress((void**)&Al,    g_Al);
    cudaGetSymbolAddress((void**)&Bh,    g_Bh);
    cudaGetSymbolAddress((void**)&Bl,    g_Bl);
    cudaGetSymbolAddress((void**)&W1h,   g_W1h);
    cudaGetSymbolAddress((void**)&W1l,   g_W1l);
    cudaGetSymbolAddress((void**)&W2h,   g_W2h);
    cudaGetSymbolAddress((void**)&W2l,   g_W2l);

    /* launches 0..4 (prologue), 5 = main GEMM (for ncu -s 5) */
    pack_w<<<(D * QLD + 255) / 256, 256>>>(Wq, Wk, Wv, Ws, bq, bk, bv, bs, Bcat, bcat);
    split_w<<<(D * QLD + 255) / 256, 256>>>(Bcat, Bh, Bl, D, D, QLD);
    split_w<<<(K1PAD * D + 255) / 256, 256>>>(W1, W1h, W1l, CDIM, K1PAD, D);
    split_w<<<(D * 64 + 255) / 256, 256>>>(W2, W2h, W2l, D, D, 64);
    gather_split_all<<<(int)(((long long)T * N_ENT * 32 + 255) / 256), 256>>>(emb, ent_x, Ah, Al);

    gemm128<1><<<dim3(QLD / 128, MPAD_E / 128, T), 256>>>(
        NULL, Ah, Al, Bh, Bl, bcat, qkvs, N_ENT, QLD, D, D, 0,
        (long long)MPAD_E * D, (long long)N_ENT * QLD);

    zero_sd<<<(int)(((long long)T * N_ENT * D / 4 + 255) / 256), 256>>>(S, denom);
    comb_init<<<(N_TX * (CDIM / 4) + 255) / 256, 256>>>(tx_x, comb);

    {
        long long nwE = (long long)T * N_TX * 32;
        long long nwN = (long long)T * N_ENT * 32;
        edge_fused_all<<<(int)((nwE + 255) / 256), 256>>>(qkvs, e_src, e_dst, S, denom);
        norm_ln_all<<<(int)((nwN + 255) / 256), 256>>>(qkvs, S, denom, ln_g, ln_b);
        scatter_all<<<(int)((nwE + 255) / 256), 256>>>(S, e_src, e_dst, comb);
    }

    gemm128<0><<<dim3(1, MPAD_T / 128, 1), 256>>>(
        comb, NULL, NULL, W1h, W1l, b1, x1, N_TX, D, CDIM, K1PAD, 1, 0, 0);
    gemm_bf16x2<<<dim3(1, (N_TX + 127) / 128), 256>>>(
        x1, W2h, W2l, b2, x2, N_TX, 64, D, D, 1);
    final_dot<<<(N_TX * 32 + 255) / 256, 256>>>(x2, W3, b3, out);
}

// round 10
// speedup vs baseline: 1.0222x; 1.0222x over previous
#include <cuda_runtime.h>
#include <cuda_bf16.h>
#include <math.h>
#include <stdint.h>
#include <stddef.h>

#define N_ENT 50000
#define N_TX  40000
#define D     128
#define F     432
#define T     11
#define CDIM  (F + T * D)      /* 1840 */
#define K1PAD 1856
#define KTXPAD 448             /* 432 padded */
#define QLD   512
#define EPS   1e-5f
#define SCALE 0.08838834764831845f

#define MPAD_E 50048           /* 391*128 */
#define MPAD_T 40064           /* 313*128 */

/* ------------------------------------------------------------------ */
__device__ float    g_qkvs[(size_t)T * N_ENT * QLD];   /* q|k|v|skip; later reused for Y */
__device__ float    g_S[(size_t)T * N_ENT * D];        /* unnormalized agg */
__device__ float    g_denom[(size_t)T * N_ENT];
__device__ float    g_x1[(size_t)MPAD_T * D];          /* b1 + tx@W1a + scatter(Y) */
__device__ float    g_x2[(size_t)N_TX * 64];
__device__ float    g_bcat[QLD];
__device__ float    g_zero128[D];                      /* stays 0 */
__device__ __nv_bfloat16 g_Ah[(size_t)T * MPAD_E * D], g_Al[(size_t)T * MPAD_E * D];
__device__ __nv_bfloat16 g_Bh[D * QLD],    g_Bl[D * QLD];
__device__ __nv_bfloat16 g_W1h[K1PAD * D], g_W1l[K1PAD * D];
__device__ __nv_bfloat16 g_W2h[D * 64],    g_W2l[D * 64];

/* ------------------------------------------------------------------ */
__device__ __forceinline__ void split1(float v, __nv_bfloat16* h, __nv_bfloat16* l) {
    __nv_bfloat16 hh = __float2bfloat16_rn(v);
    *h = hh;
    *l = __float2bfloat16_rn(v - __bfloat162float(hh));
}

/* One prologue kernel: pack+split qkv weights, split W1, split W2.    */
__global__ void prep_w(const float* __restrict__ Wq, const float* __restrict__ Wk,
                       const float* __restrict__ Wv, const float* __restrict__ Ws,
                       const float* __restrict__ bq, const float* __restrict__ bk,
                       const float* __restrict__ bv, const float* __restrict__ bs,
                       const float* __restrict__ W1, const float* __restrict__ W2,
                       __nv_bfloat16* __restrict__ Bh, __nv_bfloat16* __restrict__ Bl,
                       float* __restrict__ bcat,
                       __nv_bfloat16* __restrict__ W1h, __nv_bfloat16* __restrict__ W1l,
                       __nv_bfloat16* __restrict__ W2h, __nv_bfloat16* __restrict__ W2l) {
    int i = blockIdx.x * blockDim.x + threadIdx.x;
    const int R1 = D * QLD;              /* 65536  */
    const int R2 = R1 + K1PAD * D;       /* +237568 */
    const int R3 = R2 + D * 64;          /* +8192  */
    if (i < R1) {
        int n = i & (QLD - 1);
        int k = i >> 9;
        const float* W = (n < 128) ? Wq : (n < 256) ? Wk : (n < 384) ? Wv : Ws;
        int nn = n & 127;
        split1(W[k * 128 + nn], &Bh[i], &Bl[i]);
        if (k == 0) {
            const float* bb = (n < 128) ? bq : (n < 256) ? bk : (n < 384) ? bv : bs;
            bcat[n] = bb[nn];
        }
    } else if (i < R2) {
        int j = i - R1;
        int k = j >> 7;
        float v = (k < CDIM) ? W1[j] : 0.f;
        split1(v, &W1h[j], &W1l[j]);
    } else if (i < R3) {
        int j = i - R2;
        split1(W2[j], &W2h[j], &W2l[j]);
    }
}

__global__ void gather_split_all(const float* __restrict__ emb, const int* __restrict__ ent_x,
                                 __nv_bfloat16* __restrict__ Ah, __nv_bfloat16* __restrict__ Al) {
    long long i = (long long)blockIdx.x * blockDim.x + threadIdx.x;
    const long long TOT = (long long)T * N_ENT * (D / 4);
    if (i >= TOT) return;
    int c4  = (int)(i & 31);
    long long rowg = i >> 5;
    int t   = (int)(rowg / N_ENT);
    int row = (int)(rowg - (long long)t * N_ENT);
    int r = ent_x[rowg];
    float4 v = ((const float4*)(emb + ((size_t)t * N_ENT + r) * D))[c4];
    float vv[4] = { v.x, v.y, v.z, v.w };
    __nv_bfloat16 h[4], l[4];
#pragma unroll
    for (int j = 0; j < 4; j++) split1(vv[j], &h[j], &l[j]);
    size_t o = ((size_t)t * MPAD_E + row) * D + (c4 << 2);
    *(uint2*)(Ah + o) = *(uint2*)h;
    *(uint2*)(Al + o) = *(uint2*)l;
}

__global__ void zero_sd(float* __restrict__ S, float* __restrict__ denom) {
    long long i = (long long)blockIdx.x * blockDim.x + threadIdx.x;
    const long long S4 = (long long)T * N_ENT * D / 4;
    if (i < S4) ((float4*)S)[i] = make_float4(0.f, 0.f, 0.f, 0.f);
    if (i < (long long)T * N_ENT) denom[i] = 0.f;
}

/* ------------------------------------------------------------------ */
__device__ __forceinline__ void ldsm4(uint32_t* r, const void* p) {
    uint32_t a = (uint32_t)__cvta_generic_to_shared(p);
    asm volatile("ldmatrix.sync.aligned.m8n8.x4.shared.b16 {%0,%1,%2,%3}, [%4];"
                 : "=r"(r[0]), "=r"(r[1]), "=r"(r[2]), "=r"(r[3]) : "r"(a));
}
__device__ __forceinline__ void ldsm4t(uint32_t* r, const void* p) {
    uint32_t a = (uint32_t)__cvta_generic_to_shared(p);
    asm volatile("ldmatrix.sync.aligned.m8n8.x4.trans.shared.b16 {%0,%1,%2,%3}, [%4];"
                 : "=r"(r[0]), "=r"(r[1]), "=r"(r[2]), "=r"(r[3]) : "r"(a));
}
__device__ __forceinline__ void mma16816(float* c, const uint32_t* a, const uint32_t* b) {
    asm volatile(
        "mma.sync.aligned.m16n8k16.row.col.f32.bf16.bf16.f32 "
        "{%0,%1,%2,%3}, {%4,%5,%6,%7}, {%8,%9}, {%0,%1,%2,%3};\n"
        : "+f"(c[0]), "+f"(c[1]), "+f"(c[2]), "+f"(c[3])
        : "r"(a[0]), "r"(a[1]), "r"(a[2]), "r"(a[3]), "r"(b[0]), "r"(b[1]));
}

/* ------------------------------------------------------------------ */
/* gemm128 batched: per-z slice C = A @ B + bias. BM=BN(max)=128 BK=32 */
/* SPLITA=1: A pre-split bf16 (padded rows). SPLITA=0: A fp32, row-    */
/* guarded, split on the fly.                                          */
/* ------------------------------------------------------------------ */
#define ASTR  40
#define BSTR2 144

template<int SPLITA>
__global__ void __launch_bounds__(256) gemm128(
    const float* __restrict__ Afp,
    const __nv_bfloat16* __restrict__ Ahg, const __nv_bfloat16* __restrict__ Alg,
    const __nv_bfloat16* __restrict__ Bhg, const __nv_bfloat16* __restrict__ Blg,
    const float* __restrict__ bias, float* __restrict__ C,
    int M, int N, int Kreal, int Kpad, int relu,
    long long strideA, long long strideB, long long strideC)
{
    __shared__ __nv_bfloat16 Ahs[128][ASTR];
    __shared__ __nv_bfloat16 Als[128][ASTR];
    __shared__ __nv_bfloat16 Bhs[32][BSTR2];
    __shared__ __nv_bfloat16 Bls[32][BSTR2];

    const int tid  = threadIdx.x;
    const int lane = tid & 31;
    const int warp = tid >> 5;
    const int wm   = warp >> 1;
    const int wn   = warp & 1;
    const int m0   = blockIdx.y * 128;
    const int n0   = blockIdx.x * 128;
    const long long zA = (long long)blockIdx.z * strideA;
    const long long zB = (long long)blockIdx.z * strideB;
    const long long zC = (long long)blockIdx.z * strideC;

    const int arow  = tid >> 1;
    const int acolg = (tid & 1) << 4;
    const int brow  = tid >> 3;
    const int bcol  = (tid & 7) << 4;

    const float* afprow = NULL;
    if (!SPLITA && (m0 + arow) < M) afprow = Afp + (size_t)(m0 + arow) * Kreal;

    float acc[2][8][4];
#pragma unroll
    for (int a = 0; a < 2; a++)
#pragma unroll
        for (int b = 0; b < 8; b++)
#pragma unroll
            for (int c = 0; c < 4; c++) acc[a][b][c] = 0.f;

    uint4  sAh[2], sAl[2];
    float4 sAf[4];
    uint4  sBh[2], sBl[2];

#define LOADT(K0)                                                              \
    do {                                                                       \
        if (SPLITA) {                                                          \
            size_t ao = (size_t)(zA + (long long)(m0 + arow) * Kreal           \
                                 + (K0) + acolg);                              \
            sAh[0] = *(const uint4*)(Ahg + ao);                                \
            sAh[1] = *(const uint4*)(Ahg + ao + 8);                            \
            sAl[0] = *(const uint4*)(Alg + ao);                                \
            sAl[1] = *(const uint4*)(Alg + ao + 8);                            \
        } else {                                                               \
            if (afprow && (K0) + acolg < Kreal) {                              \
                const float4* p = (const float4*)(afprow + (K0) + acolg);      \
                sAf[0] = p[0]; sAf[1] = p[1]; sAf[2] = p[2]; sAf[3] = p[3];    \
            } else {                                                           \
                sAf[0] = sAf[1] = sAf[2] = sAf[3] =                            \
                    make_float4(0.f, 0.f, 0.f, 0.f);                           \
            }                                                                  \
        }                                                                      \
        size_t bo = (size_t)(zB + (long long)((K0) + brow) * N + n0 + bcol);   \
        sBh[0] = *(const uint4*)(Bhg + bo);                                    \
        sBh[1] = *(const uint4*)(Bhg + bo + 8);                                \
        sBl[0] = *(const uint4*)(Blg + bo);                                    \
        sBl[1] = *(const uint4*)(Blg + bo + 8);                                \
    } while (0)

    LOADT(0);

    for (int k0 = 0; k0 < Kpad; k0 += 32) {
        if (SPLITA) {
            *(uint4*)&Ahs[arow][acolg]     = sAh[0];
            *(uint4*)&Ahs[arow][acolg + 8] = sAh[1];
            *(uint4*)&Als[arow][acolg]     = sAl[0];
            *(uint4*)&Als[arow][acolg + 8] = sAl[1];
        } else {
            const float* fv = (const float*)sAf;
#pragma unroll
            for (int j = 0; j < 8; j++) {
                __nv_bfloat16 h0, l0, h1, l1;
                split1(fv[2 * j], &h0, &l0);
                split1(fv[2 * j + 1], &h1, &l1);
                __nv_bfloat162 hp; hp.x = h0; hp.y = h1;
                __nv_bfloat162 lp; lp.x = l0; lp.y = l1;
                *(__nv_bfloat162*)&Ahs[arow][acolg + 2 * j] = hp;
                *(__nv_bfloat162*)&Als[arow][acolg + 2 * j] = lp;
            }
        }
        *(uint4*)&Bhs[brow][bcol]     = sBh[0];
        *(uint4*)&Bhs[brow][bcol + 8] = sBh[1];
        *(uint4*)&Bls[brow][bcol]     = sBl[0];
        *(uint4*)&Bls[brow][bcol + 8] = sBl[1];
        __syncthreads();

        int kn = k0 + 32;
        if (kn < Kpad) LOADT(kn);

#pragma unroll
        for (int ks = 0; ks < 2; ks++) {
            const int kk = ks << 4;
            uint32_t afh[2][4], afl[2][4];
#pragma unroll
            for (int mt = 0; mt < 2; mt++) {
                const int r = wm * 32 + mt * 16 + (lane & 15);
                const int c = kk + ((lane >> 4) << 3);
                ldsm4(afh[mt], &Ahs[r][c]);
                ldsm4(afl[mt], &Als[r][c]);
            }
            uint32_t bfh[4][4], bfl[4][4];
#pragma unroll
            for (int nc = 0; nc < 4; nc++) {
                const int r = kk + (lane & 15);
                const int c = wn * 64 + nc * 16 + ((lane >> 4) << 3);
                ldsm4t(bfh[nc], &Bhs[r][c]);
                ldsm4t(bfl[nc], &Bls[r][c]);
            }
#pragma unroll
            for (int mt = 0; mt < 2; mt++)
#pragma unroll
                for (int nt = 0; nt < 8; nt++) {
                    const int nc = nt >> 1, p = (nt & 1) << 1;
                    uint32_t bh2[2] = { bfh[nc][p], bfh[nc][p + 1] };
                    uint32_t bl2[2] = { bfl[nc][p], bfl[nc][p + 1] };
                    mma16816(acc[mt][nt], afh[mt], bh2);
                    mma16816(acc[mt][nt], afl[mt], bh2);
                    mma16816(acc[mt][nt], afh[mt], bl2);
                }
        }
        __syncthreads();
    }
#undef LOADT

#pragma unroll
    for (int mt = 0; mt < 2; mt++)
#pragma unroll
        for (int nt = 0; nt < 8; nt++) {
            const int col = n0 + wn * 64 + nt * 8 + ((lane & 3) << 1);
            const float bx = bias[col], by = bias[col + 1];
            const int r0 = m0 + wm * 32 + mt * 16 + (lane >> 2);
            float o0 = acc[mt][nt][0] + bx, o1 = acc[mt][nt][1] + by;
            float o2 = acc[mt][nt][2] + bx, o3 = acc[mt][nt][3] + by;
            if (relu) {
                o0 = fmaxf(o0, 0.f); o1 = fmaxf(o1, 0.f);
                o2 = fmaxf(o2, 0.f); o3 = fmaxf(o3, 0.f);
            }
            if (r0 < M)     { float2 v = make_float2(o0, o1);
                              *(float2*)(C + zC + (size_t)r0 * N + col) = v; }
            if (r0 + 8 < M) { float2 v = make_float2(o2, o3);
                              *(float2*)(C + zC + (size_t)(r0 + 8) * N + col) = v; }
        }
}

/* ------------------------------------------------------------------ */
/* BN=64 GEMM for classifier GEMM2 (N=64); optional ReLU on A load.    */
/* ------------------------------------------------------------------ */
#define BSTR 72
__global__ void __launch_bounds__(256) gemm_bf16x2(
    const float* __restrict__ A,
    const __nv_bfloat16* __restrict__ Bhg, const __nv_bfloat16* __restrict__ Blg,
    const float* __restrict__ bias, float* __restrict__ C,
    int M, int N, int Kreal, int Kpad, int relu, int reluA)
{
    __shared__ __nv_bfloat16 Ah[128][ASTR];
    __shared__ __nv_bfloat16 Al[128][ASTR];
    __shared__ __nv_bfloat16 Bhs[32][BSTR];
    __shared__ __nv_bfloat16 Bls[32][BSTR];

    const int tid  = threadIdx.x;
    const int lane = tid & 31;
    const int warp = tid >> 5;
    const int wm   = warp >> 1;
    const int wn   = warp & 1;
    const int m0   = blockIdx.y * 128;
    const int n0   = blockIdx.x * 64;

    const int arow  = tid >> 1;
    const int acolg = (tid & 1) << 4;
    const float* aptr = NULL;
    {
        int gm = m0 + arow;
        if (gm < M) aptr = A + (size_t)gm * Kreal;
    }
    const int brow  = tid >> 3;
    const int bcolg = (tid & 7) << 3;

    float acc[2][4][4];
#pragma unroll
    for (int i = 0; i < 2; i++)
#pragma unroll
        for (int j = 0; j < 4; j++)
#pragma unroll
            for (int l = 0; l < 4; l++) acc[i][j][l] = 0.f;

    for (int k0 = 0; k0 < Kpad; k0 += 32) {
        float4 f[4];
        if (aptr && (k0 + acolg) < Kreal) {
            const float4* p = (const float4*)(aptr + k0 + acolg);
            f[0] = p[0]; f[1] = p[1]; f[2] = p[2]; f[3] = p[3];
        } else {
            f[0] = f[1] = f[2] = f[3] = make_float4(0.f, 0.f, 0.f, 0.f);
        }
        float* fv = (float*)f;
        if (reluA) {
#pragma unroll
            for (int j = 0; j < 16; j++) fv[j] = fmaxf(fv[j], 0.f);
        }
#pragma unroll
        for (int j = 0; j < 8; j++) {
            __nv_bfloat16 h0, l0, h1, l1;
            split1(fv[2 * j], &h0, &l0);
            split1(fv[2 * j + 1], &h1, &l1);
            __nv_bfloat162 hp; hp.x = h0; hp.y = h1;
            __nv_bfloat162 lp; lp.x = l0; lp.y = l1;
            *(__nv_bfloat162*)&Ah[arow][acolg + 2 * j] = hp;
            *(__nv_bfloat162*)&Al[arow][acolg + 2 * j] = lp;
        }
        {
            size_t off = (size_t)(k0 + brow) * N + n0 + bcolg;
            uint4 vh = *(const uint4*)(Bhg + off);
            uint4 vl = *(const uint4*)(Blg + off);
            *(uint4*)&Bhs[brow][bcolg] = vh;
            *(uint4*)&Bls[brow][bcolg] = vl;
        }
        __syncthreads();

#pragma unroll
        for (int ks = 0; ks < 2; ks++) {
            const int kk = ks << 4;
            uint32_t afh[2][4], afl[2][4];
#pragma unroll
            for (int mt = 0; mt < 2; mt++) {
                const int r = wm * 32 + mt * 16 + (lane & 15);
                const int c = kk + ((lane >> 4) << 3);
                ldsm4(afh[mt], &Ah[r][c]);
                ldsm4(afl[mt], &Al[r][c]);
            }
            uint32_t bfh[2][4], bfl[2][4];
#pragma unroll
            for (int nc = 0; nc < 2; nc++) {
                const int r = kk + (lane & 15);
                const int c = wn * 32 + nc * 16 + ((lane >> 4) << 3);
                ldsm4t(bfh[nc], &Bhs[r][c]);
                ldsm4t(bfl[nc], &Bls[r][c]);
            }
#pragma unroll
            for (int mt = 0; mt < 2; mt++)
#pragma unroll
                for (int nt = 0; nt < 4; nt++) {
                    const int nc = nt >> 1, p = (nt & 1) << 1;
                    uint32_t bh2[2] = { bfh[nc][p], bfh[nc][p + 1] };
                    uint32_t bl2[2] = { bfl[nc][p], bfl[nc][p + 1] };
                    mma16816(acc[mt][nt], afh[mt], bh2);
                    mma16816(acc[mt][nt], afl[mt], bh2);
                    mma16816(acc[mt][nt], afh[mt], bl2);
                }
        }
        __syncthreads();
    }

#pragma unroll
    for (int mt = 0; mt < 2; mt++)
#pragma unroll
        for (int nt = 0; nt < 4; nt++) {
            const int col = n0 + wn * 32 + nt * 8 + ((lane & 3) << 1);
            const float bx = bias[col], by = bias[col + 1];
            const int r0 = m0 + wm * 32 + mt * 16 + (lane >> 2);
            float o0 = acc[mt][nt][0] + bx, o1 = acc[mt][nt][1] + by;
            float o2 = acc[mt][nt][2] + bx, o3 = acc[mt][nt][3] + by;
            if (relu) {
                o0 = fmaxf(o0, 0.f); o1 = fmaxf(o1, 0.f);
                o2 = fmaxf(o2, 0.f); o3 = fmaxf(o3, 0.f);
            }
            if (r0 < M)     { float2 v = make_float2(o0, o1); *(float2*)(C + (size_t)r0 * N + col) = v; }
            if (r0 + 8 < M) { float2 v = make_float2(o2, o3); *(float2*)(C + (size_t)(r0 + 8) * N + col) = v; }
        }
}

/* ------------------------------------------------------------------ */
/* Edge pass (all types): ex = exp(dot(q[dst],k[src])*scale);          */
/* denom[dst] += ex;  S[dst] += ex * v[src]                            */
/* ------------------------------------------------------------------ */
__global__ void edge_fused_all(const float* __restrict__ qkvs,
                               const int* __restrict__ e_src, const int* __restrict__ e_dst,
                               float* __restrict__ S, float* __restrict__ denom) {
    long long w = ((long long)blockIdx.x * blockDim.x + threadIdx.x) >> 5;
    int lane = threadIdx.x & 31;
    if (w >= (long long)T * N_TX) return;
    int t = (int)(w / N_TX);
    int e = (int)(w - (long long)t * N_TX);
    int dd = e_dst[(size_t)t * N_TX + e];
    int ss = e_src[(size_t)t * N_TX + e];
    const float* qk = qkvs + (size_t)t * N_ENT * QLD;
    float4 qv = ((const float4*)(qk + (size_t)dd * QLD))[lane];
    float4 kv = ((const float4*)(qk + (size_t)ss * QLD + 128))[lane];
    float acc = qv.x * kv.x + qv.y * kv.y + qv.z * kv.z + qv.w * kv.w;
#pragma unroll
    for (int o = 16; o; o >>= 1) acc += __shfl_xor_sync(0xFFFFFFFFu, acc, o);
    float exv = expf(acc * SCALE);   /* |score| << 1: no max-shift needed */
    float4 vv = ((const float4*)(qk + (size_t)ss * QLD + 256))[lane];
    float* so = S + ((size_t)t * N_ENT + dd) * D + (lane << 2);
    atomicAdd(so + 0, exv * vv.x);
    atomicAdd(so + 1, exv * vv.y);
    atomicAdd(so + 2, exv * vv.z);
    atomicAdd(so + 3, exv * vv.w);
    if (lane == 0) atomicAdd(&denom[(size_t)t * N_ENT + dd], exv);
}

/* ------------------------------------------------------------------ */
/* Per-node: hn = LN(skip + S/denom), emitted as bf16 hi/lo into Ah/Al */
/* ------------------------------------------------------------------ */
__global__ void norm_ln_all(const float* __restrict__ qkvs,
                            const float* __restrict__ S, const float* __restrict__ denom,
                            const float* __restrict__ ln_g, const float* __restrict__ ln_b,
                            __nv_bfloat16* __restrict__ Hh, __nv_bfloat16* __restrict__ Hl) {
    long long w = ((long long)blockIdx.x * blockDim.x + threadIdx.x) >> 5;
    int lane = threadIdx.x & 31;
    if (w >= (long long)T * N_ENT) return;
    int t = (int)(w / N_ENT);
    int n = (int)(w - (long long)t * N_ENT);
    long long node = w;

    float4 skip = ((const float4*)(qkvs + (size_t)node * QLD + 384))[lane];
    float dn = denom[node];
    float inv = (dn > 0.f) ? (1.f / dn) : 0.f;
    float4 sv = ((const float4*)(S + (size_t)node * D))[lane];
    float x0 = skip.x + sv.x * inv;
    float x1 = skip.y + sv.y * inv;
    float x2 = skip.z + sv.z * inv;
    float x3 = skip.w + sv.w * inv;

    float s = x0 + x1 + x2 + x3;
#pragma unroll
    for (int o = 16; o; o >>= 1) s += __shfl_xor_sync(0xFFFFFFFFu, s, o);
    float mu = s * (1.f / 128.f);
    float d0 = x0 - mu, d1 = x1 - mu, d2 = x2 - mu, d3 = x3 - mu;
    float v = d0 * d0 + d1 * d1 + d2 * d2 + d3 * d3;
#pragma unroll
    for (int o = 16; o; o >>= 1) v += __shfl_xor_sync(0xFFFFFFFFu, v, o);
    float rstd = rsqrtf(v * (1.f / 128.f) + EPS);

    float4 gg = ((const float4*)(ln_g + t * D))[lane];
    float4 bb = ((const float4*)(ln_b + t * D))[lane];
    float hv[4];
    hv[0] = d0 * rstd * gg.x + bb.x;
    hv[1] = d1 * rstd * gg.y + bb.y;
    hv[2] = d2 * rstd * gg.z + bb.z;
    hv[3] = d3 * rstd * gg.w + bb.w;
    __nv_bfloat16 h[4], l[4];
#pragma unroll
    for (int j = 0; j < 4; j++) split1(hv[j], &h[j], &l[j]);
    size_t o = ((size_t)t * MPAD_E + n) * D + (lane << 2);
    *(uint2*)(Hh + o) = *(uint2*)h;
    *(uint2*)(Hl + o) = *(uint2*)l;
}

/* per edge: x1[dst, 0:128] += Y_t[src]  (x1 is 20 MB: L2-resident)    */
__global__ void scatter_all(const float* __restrict__ Y,
                            const int* __restrict__ e_src, const int* __restrict__ e_dst,
                            float* __restrict__ x1) {
    long long w = ((long long)blockIdx.x * blockDim.x + threadIdx.x) >> 5;
    int lane = threadIdx.x & 31;
    if (w >= (long long)T * N_TX) return;
    int t = (int)(w / N_TX);
    int e = (int)(w - (long long)t * N_TX);
    int ss = e_src[(size_t)t * N_TX + e];
    int dd = e_dst[(size_t)t * N_TX + e];
    float4 hv = ((const float4*)(Y + ((size_t)t * MPAD_E + ss) * D))[lane];
    float* c = x1 + (size_t)dd * D + (lane << 2);
    atomicAdd(c + 0, hv.x);
    atomicAdd(c + 1, hv.y);
    atomicAdd(c + 2, hv.z);
    atomicAdd(c + 3, hv.w);
}

__global__ void final_dot(const float* __restrict__ x2, const float* __restrict__ W3,
                          const float* __restrict__ b3, float* __restrict__ out) {
    int r = (blockIdx.x * blockDim.x + threadIdx.x) >> 5;
    int lane = threadIdx.x & 31;
    if (r >= N_TX) return;
    float2 xv = ((const float2*)(x2 + (size_t)r * 64))[lane];
    float2 wv = ((const float2*)W3)[lane];
    float s = xv.x * wv.x + xv.y * wv.y;
#pragma unroll
    for (int o = 16; o; o >>= 1) s += __shfl_xor_sync(0xFFFFFFFFu, s, o);
    if (lane == 0) out[r] = s + b3[0];
}

/* ------------------------------------------------------------------ */
extern "C" void kernel_launch(void* const* d_in, const int* in_sizes, int n_in,
                              void* d_out, int out_size) {
    const float* tx_x  = (const float*)d_in[0];
    const int*   ent_x = (const int*)d_in[1];
    const int*   e_src = (const int*)d_in[2];
    const int*   e_dst = (const int*)d_in[3];
    const float* emb   = (const float*)d_in[4];
    const float* ln_g  = (const float*)d_in[5];
    const float* ln_b  = (const float*)d_in[6];
    const float* Wq = (const float*)d_in[7];  const float* bq = (const float*)d_in[8];
    const float* Wk = (const float*)d_in[9];  const float* bk = (const float*)d_in[10];
    const float* Wv = (const float*)d_in[11]; const float* bv = (const float*)d_in[12];
    const float* Ws = (const float*)d_in[13]; const float* bs = (const float*)d_in[14];
    const float* W1 = (const float*)d_in[15]; const float* b1 = (const float*)d_in[16];
    const float* W2 = (const float*)d_in[17]; const float* b2 = (const float*)d_in[18];
    const float* W3 = (const float*)d_in[19]; const float* b3 = (const float*)d_in[20];
    float* out = (float*)d_out;

    float *qkvs, *S, *denom, *x1, *x2, *bcat, *zero128;
    __nv_bfloat16 *Ah, *Al, *Bh, *Bl, *W1h, *W1l, *W2h, *W2l;
    cudaGetSymbolAddress((void**)&qkvs,   g_qkvs);
    cudaGetSymbolAddress((void**)&S,      g_S);
    cudaGetSymbolAddress((void**)&denom,  g_denom);
    cudaGetSymbolAddress((void**)&x1,     g_x1);
    cudaGetSymbolAddress((void**)&x2,     g_x2);
    cudaGetSymbolAddress((void**)&bcat,   g_bcat);
    cudaGetSymbolAddress((void**)&zero128, g_zero128);
    cudaGetSymbolAddress((void**)&Ah,     g_Ah);
    cudaGetSymbolAddress((void**)&Al,     g_Al);
    cudaGetSymbolAddress((void**)&Bh,     g_Bh);
    cudaGetSymbolAddress((void**)&Bl,     g_Bl);
    cudaGetSymbolAddress((void**)&W1h,    g_W1h);
    cudaGetSymbolAddress((void**)&W1l,    g_W1l);
    cudaGetSymbolAddress((void**)&W2h,    g_W2h);
    cudaGetSymbolAddress((void**)&W2l,    g_W2l);

    const int PREP_TOT = D * QLD + K1PAD * D + D * 64;

    /* 0 */ prep_w<<<(PREP_TOT + 255) / 256, 256>>>(Wq, Wk, Wv, Ws, bq, bk, bv, bs,
                                                    W1, W2, Bh, Bl, bcat, W1h, W1l, W2h, W2l);
    /* 1 */ gather_split_all<<<(int)(((long long)T * N_ENT * 32 + 255) / 256), 256>>>(emb, ent_x, Ah, Al);
    /* 2 */ zero_sd<<<(int)(((long long)T * N_ENT * D / 4 + 255) / 256), 256>>>(S, denom);
    /* 3: x1 = b1 + tx @ W1[0:432]  (rows padded to MPAD_T) */
    gemm128<0><<<dim3(1, MPAD_T / 128, 1), 256>>>(
        tx_x, NULL, NULL, W1h, W1l, b1, x1, N_TX, D, F, KTXPAD, 0, 0, 0, 0);
    /* 4: batched q|k|v|skip GEMM */
    gemm128<1><<<dim3(QLD / 128, MPAD_E / 128, T), 256>>>(
        NULL, Ah, Al, Bh, Bl, bcat, qkvs, N_ENT, QLD, D, D, 0,
        (long long)MPAD_E * D, 0, (long long)N_ENT * QLD);
    /* 5: edge pass (ncu target) */
    {
        long long nwE = (long long)T * N_TX * 32;
        edge_fused_all<<<(int)((nwE + 255) / 256), 256>>>(qkvs, e_src, e_dst, S, denom);
    }
    /* 6: per-node normalize + LN -> bf16 hn into Ah/Al (reuse) */
    {
        long long nwN = (long long)T * N_ENT * 32;
        norm_ln_all<<<(int)((nwN + 255) / 256), 256>>>(qkvs, S, denom, ln_g, ln_b, Ah, Al);
    }
    /* 7: Y_t = hn_t @ W1_t   (Y reuses qkvs buffer; B slice per z) */
    gemm128<1><<<dim3(1, MPAD_E / 128, T), 256>>>(
        NULL, Ah, Al, W1h + (size_t)F * D, W1l + (size_t)F * D, zero128, qkvs,
        N_ENT, D, D, D, 0,
        (long long)MPAD_E * D, (long long)D * D, (long long)MPAD_E * D);
    /* 8: x1[dst] += Y[src] */
    {
        long long nwE = (long long)T * N_TX * 32;
        scatter_all<<<(int)((nwE + 255) / 256), 256>>>(qkvs, e_src, e_dst, x1);
    }
    /* 9: x2 = relu(relu(x1) @ W2 + b2)  (ReLU on A load) */
    gemm_bf16x2<<<dim3(1, (N_TX + 127) / 128), 256>>>(
        x1, W2h, W2l, b2, x2, N_TX, 64, D, D, 1, 1);
    /* 10 */ final_dot<<<(N_TX * 32 + 255) / 256, 256>>>(x2, W3, b3, out);
}

// round 11
// speedup vs baseline: 1.1102x; 1.0861x over previous
#include <cuda_runtime.h>
#include <cuda_bf16.h>
#include <math.h>
#include <stdint.h>
#include <stddef.h>

#define N_ENT 50000
#define N_TX  40000
#define D     128
#define F     432
#define T     11
#define CDIM  (F + T * D)      /* 1840 */
#define K1PAD 1856
#define KTXPAD 448             /* 432 padded */
#define QLD   512
#define EPS   1e-5f
#define SCALE 0.08838834764831845f

#define MPAD_E 50048           /* 391*128 */
#define MPAD_T 40064           /* 313*128 */

/* ------------------------------------------------------------------ */
__device__ float    g_qkvs[(size_t)T * N_ENT * QLD];   /* q|k|v|skip; later reused for Y */
__device__ float    g_S[(size_t)T * N_ENT * D];        /* unnormalized agg */
__device__ float    g_denom[(size_t)T * N_ENT];
__device__ float    g_x1[(size_t)MPAD_T * D];          /* b1 + tx@W1a + scatter(Y) */
__device__ float    g_x2[(size_t)N_TX * 64];
__device__ float    g_bcat[QLD];
__device__ float    g_zero128[D];                      /* stays 0 */
__device__ __nv_bfloat16 g_Ah[(size_t)T * MPAD_E * D], g_Al[(size_t)T * MPAD_E * D];
__device__ __nv_bfloat16 g_Bh[D * QLD],    g_Bl[D * QLD];
__device__ __nv_bfloat16 g_W1h[K1PAD * D], g_W1l[K1PAD * D];
__device__ __nv_bfloat16 g_W2h[D * 64],    g_W2l[D * 64];

/* ------------------------------------------------------------------ */
__device__ __forceinline__ void split1(float v, __nv_bfloat16* h, __nv_bfloat16* l) {
    __nv_bfloat16 hh = __float2bfloat16_rn(v);
    *h = hh;
    *l = __float2bfloat16_rn(v - __bfloat162float(hh));
}

/* One prologue kernel: pack+split qkv weights, split W1, split W2.    */
__global__ void prep_w(const float* __restrict__ Wq, const float* __restrict__ Wk,
                       const float* __restrict__ Wv, const float* __restrict__ Ws,
                       const float* __restrict__ bq, const float* __restrict__ bk,
                       const float* __restrict__ bv, const float* __restrict__ bs,
                       const float* __restrict__ W1, const float* __restrict__ W2,
                       __nv_bfloat16* __restrict__ Bh, __nv_bfloat16* __restrict__ Bl,
                       float* __restrict__ bcat,
                       __nv_bfloat16* __restrict__ W1h, __nv_bfloat16* __restrict__ W1l,
                       __nv_bfloat16* __restrict__ W2h, __nv_bfloat16* __restrict__ W2l) {
    int i = blockIdx.x * blockDim.x + threadIdx.x;
    const int R1 = D * QLD;              /* 65536  */
    const int R2 = R1 + K1PAD * D;       /* +237568 */
    const int R3 = R2 + D * 64;          /* +8192  */
    if (i < R1) {
        int n = i & (QLD - 1);
        int k = i >> 9;
        const float* W = (n < 128) ? Wq : (n < 256) ? Wk : (n < 384) ? Wv : Ws;
        int nn = n & 127;
        split1(W[k * 128 + nn], &Bh[i], &Bl[i]);
        if (k == 0) {
            const float* bb = (n < 128) ? bq : (n < 256) ? bk : (n < 384) ? bv : bs;
            bcat[n] = bb[nn];
        }
    } else if (i < R2) {
        int j = i - R1;
        int k = j >> 7;
        float v = (k < CDIM) ? W1[j] : 0.f;
        split1(v, &W1h[j], &W1l[j]);
    } else if (i < R3) {
        int j = i - R2;
        split1(W2[j], &W2h[j], &W2l[j]);
    }
}

__global__ void gather_split_all(const float* __restrict__ emb, const int* __restrict__ ent_x,
                                 __nv_bfloat16* __restrict__ Ah, __nv_bfloat16* __restrict__ Al) {
    long long i = (long long)blockIdx.x * blockDim.x + threadIdx.x;
    const long long TOT = (long long)T * N_ENT * (D / 4);
    if (i >= TOT) return;
    int c4  = (int)(i & 31);
    long long rowg = i >> 5;
    int t   = (int)(rowg / N_ENT);
    int row = (int)(rowg - (long long)t * N_ENT);
    int r = ent_x[rowg];
    float4 v = ((const float4*)(emb + ((size_t)t * N_ENT + r) * D))[c4];
    float vv[4] = { v.x, v.y, v.z, v.w };
    __nv_bfloat16 h[4], l[4];
#pragma unroll
    for (int j = 0; j < 4; j++) split1(vv[j], &h[j], &l[j]);
    size_t o = ((size_t)t * MPAD_E + row) * D + (c4 << 2);
    *(uint2*)(Ah + o) = *(uint2*)h;
    *(uint2*)(Al + o) = *(uint2*)l;
}

__global__ void zero_sd(float* __restrict__ S, float* __restrict__ denom) {
    long long i = (long long)blockIdx.x * blockDim.x + threadIdx.x;
    const long long S4 = (long long)T * N_ENT * D / 4;
    if (i < S4) ((float4*)S)[i] = make_float4(0.f, 0.f, 0.f, 0.f);
    if (i < (long long)T * N_ENT) denom[i] = 0.f;
}

/* ------------------------------------------------------------------ */
__device__ __forceinline__ void ldsm4(uint32_t* r, const void* p) {
    uint32_t a = (uint32_t)__cvta_generic_to_shared(p);
    asm volatile("ldmatrix.sync.aligned.m8n8.x4.shared.b16 {%0,%1,%2,%3}, [%4];"
                 : "=r"(r[0]), "=r"(r[1]), "=r"(r[2]), "=r"(r[3]) : "r"(a));
}
__device__ __forceinline__ void ldsm4t(uint32_t* r, const void* p) {
    uint32_t a = (uint32_t)__cvta_generic_to_shared(p);
    asm volatile("ldmatrix.sync.aligned.m8n8.x4.trans.shared.b16 {%0,%1,%2,%3}, [%4];"
                 : "=r"(r[0]), "=r"(r[1]), "=r"(r[2]), "=r"(r[3]) : "r"(a));
}
__device__ __forceinline__ void mma16816(float* c, const uint32_t* a, const uint32_t* b) {
    asm volatile(
        "mma.sync.aligned.m16n8k16.row.col.f32.bf16.bf16.f32 "
        "{%0,%1,%2,%3}, {%4,%5,%6,%7}, {%8,%9}, {%0,%1,%2,%3};\n"
        : "+f"(c[0]), "+f"(c[1]), "+f"(c[2]), "+f"(c[3])
        : "r"(a[0]), "r"(a[1]), "r"(a[2]), "r"(a[3]), "r"(b[0]), "r"(b[1]));
}

/* ------------------------------------------------------------------ */
/* gemm128 batched, 512 threads: per-z C = A @ B + bias.               */
/* BM=BN=128 BK=32, 16 warps 4x4, warp tile 32x32 (acc 32 regs/thr).   */
/* SPLITA=1: A pre-split bf16 (padded rows). SPLITA=0: A fp32, row-    */
/* guarded, split on the fly.                                          */
/* ------------------------------------------------------------------ */
#define ASTR  40
#define BSTR2 136

template<int SPLITA>
__global__ void __launch_bounds__(512) gemm128(
    const float* __restrict__ Afp,
    const __nv_bfloat16* __restrict__ Ahg, const __nv_bfloat16* __restrict__ Alg,
    const __nv_bfloat16* __restrict__ Bhg, const __nv_bfloat16* __restrict__ Blg,
    const float* __restrict__ bias, float* __restrict__ C,
    int M, int N, int Kreal, int Kpad, int relu,
    long long strideA, long long strideB, long long strideC)
{
    __shared__ __nv_bfloat16 Ahs[128][ASTR];
    __shared__ __nv_bfloat16 Als[128][ASTR];
    __shared__ __nv_bfloat16 Bhs[32][BSTR2];
    __shared__ __nv_bfloat16 Bls[32][BSTR2];

    const int tid  = threadIdx.x;
    const int lane = tid & 31;
    const int warp = tid >> 5;          /* 0..15 */
    const int wm   = warp >> 2;         /* 0..3  */
    const int wn   = warp & 3;          /* 0..3  */
    const int m0   = blockIdx.y * 128;
    const int n0   = blockIdx.x * 128;
    const long long zA = (long long)blockIdx.z * strideA;
    const long long zB = (long long)blockIdx.z * strideB;
    const long long zC = (long long)blockIdx.z * strideC;

    const int arow  = tid >> 2;          /* 0..127 */
    const int acolg = (tid & 3) << 3;    /* 0,8,16,24 */
    const int brow  = tid >> 4;          /* 0..31  */
    const int bcolg = (tid & 15) << 3;   /* 0..120 */

    const float* afprow = NULL;
    if (!SPLITA && (m0 + arow) < M) afprow = Afp + (size_t)(m0 + arow) * Kreal;

    float acc[2][4][4];
#pragma unroll
    for (int a = 0; a < 2; a++)
#pragma unroll
        for (int b = 0; b < 4; b++)
#pragma unroll
            for (int c = 0; c < 4; c++) acc[a][b][c] = 0.f;

    uint4  sAh, sAl;
    float4 sAf[2];
    uint4  sBh, sBl;

#define LOADT(K0)                                                              \
    do {                                                                       \
        if (SPLITA) {                                                          \
            size_t ao = (size_t)(zA + (long long)(m0 + arow) * Kreal           \
                                 + (K0) + acolg);                              \
            sAh = *(const uint4*)(Ahg + ao);                                   \
            sAl = *(const uint4*)(Alg + ao);                                   \
        } else {                                                               \
            if (afprow && (K0) + acolg < Kreal) {                              \
                const float4* p = (const float4*)(afprow + (K0) + acolg);      \
                sAf[0] = p[0]; sAf[1] = p[1];                                  \
            } else {                                                           \
                sAf[0] = sAf[1] = make_float4(0.f, 0.f, 0.f, 0.f);             \
            }                                                                  \
        }                                                                      \
        size_t bo = (size_t)(zB + (long long)((K0) + brow) * N + n0 + bcolg);  \
        sBh = *(const uint4*)(Bhg + bo);                                       \
        sBl = *(const uint4*)(Blg + bo);                                       \
    } while (0)

    LOADT(0);

    for (int k0 = 0; k0 < Kpad; k0 += 32) {
        if (SPLITA) {
            *(uint4*)&Ahs[arow][acolg] = sAh;
            *(uint4*)&Als[arow][acolg] = sAl;
        } else {
            const float* fv = (const float*)sAf;
#pragma unroll
            for (int j = 0; j < 4; j++) {
                __nv_bfloat16 h0, l0, h1, l1;
                split1(fv[2 * j], &h0, &l0);
                split1(fv[2 * j + 1], &h1, &l1);
                __nv_bfloat162 hp; hp.x = h0; hp.y = h1;
                __nv_bfloat162 lp; lp.x = l0; lp.y = l1;
                *(__nv_bfloat162*)&Ahs[arow][acolg + 2 * j] = hp;
                *(__nv_bfloat162*)&Als[arow][acolg + 2 * j] = lp;
            }
        }
        *(uint4*)&Bhs[brow][bcolg] = sBh;
        *(uint4*)&Bls[brow][bcolg] = sBl;
        __syncthreads();

        int kn = k0 + 32;
        if (kn < Kpad) LOADT(kn);

#pragma unroll
        for (int ks = 0; ks < 2; ks++) {
            const int kk = ks << 4;
            uint32_t afh[2][4], afl[2][4];
#pragma unroll
            for (int mt = 0; mt < 2; mt++) {
                const int r = wm * 32 + mt * 16 + (lane & 15);
                const int c = kk + ((lane >> 4) << 3);
                ldsm4(afh[mt], &Ahs[r][c]);
                ldsm4(afl[mt], &Als[r][c]);
            }
            uint32_t bfh[2][4], bfl[2][4];
#pragma unroll
            for (int nc = 0; nc < 2; nc++) {
                const int r = kk + (lane & 15);
                const int c = wn * 32 + nc * 16 + ((lane >> 4) << 3);
                ldsm4t(bfh[nc], &Bhs[r][c]);
                ldsm4t(bfl[nc], &Bls[r][c]);
            }
#pragma unroll
            for (int mt = 0; mt < 2; mt++)
#pragma unroll
                for (int nt = 0; nt < 4; nt++) {
                    const int nc = nt >> 1, p = (nt & 1) << 1;
                    uint32_t bh2[2] = { bfh[nc][p], bfh[nc][p + 1] };
                    uint32_t bl2[2] = { bfl[nc][p], bfl[nc][p + 1] };
                    mma16816(acc[mt][nt], afh[mt], bh2);
                    mma16816(acc[mt][nt], afl[mt], bh2);
                    mma16816(acc[mt][nt], afh[mt], bl2);
                }
        }
        __syncthreads();
    }
#undef LOADT

#pragma unroll
    for (int mt = 0; mt < 2; mt++)
#pragma unroll
        for (int nt = 0; nt < 4; nt++) {
            const int col = n0 + wn * 32 + nt * 8 + ((lane & 3) << 1);
            const float bx = bias[col], by = bias[col + 1];
            const int r0 = m0 + wm * 32 + mt * 16 + (lane >> 2);
            float o0 = acc[mt][nt][0] + bx, o1 = acc[mt][nt][1] + by;
            float o2 = acc[mt][nt][2] + bx, o3 = acc[mt][nt][3] + by;
            if (relu) {
                o0 = fmaxf(o0, 0.f); o1 = fmaxf(o1, 0.f);
                o2 = fmaxf(o2, 0.f); o3 = fmaxf(o3, 0.f);
            }
            if (r0 < M)     { float2 v = make_float2(o0, o1);
                              *(float2*)(C + zC + (size_t)r0 * N + col) = v; }
            if (r0 + 8 < M) { float2 v = make_float2(o2, o3);
                              *(float2*)(C + zC + (size_t)(r0 + 8) * N + col) = v; }
        }
}

/* ------------------------------------------------------------------ */
/* BN=64 GEMM for classifier GEMM2 (N=64); optional ReLU on A load.    */
/* ------------------------------------------------------------------ */
#define BSTR 72
__global__ void __launch_bounds__(256) gemm_bf16x2(
    const float* __restrict__ A,
    const __nv_bfloat16* __restrict__ Bhg, const __nv_bfloat16* __restrict__ Blg,
    const float* __restrict__ bias, float* __restrict__ C,
    int M, int N, int Kreal, int Kpad, int relu, int reluA)
{
    __shared__ __nv_bfloat16 Ah[128][ASTR];
    __shared__ __nv_bfloat16 Al[128][ASTR];
    __shared__ __nv_bfloat16 Bhs[32][BSTR];
    __shared__ __nv_bfloat16 Bls[32][BSTR];

    const int tid  = threadIdx.x;
    const int lane = tid & 31;
    const int warp = tid >> 5;
    const int wm   = warp >> 1;
    const int wn   = warp & 1;
    const int m0   = blockIdx.y * 128;
    const int n0   = blockIdx.x * 64;

    const int arow  = tid >> 1;
    const int acolg = (tid & 1) << 4;
    const float* aptr = NULL;
    {
        int gm = m0 + arow;
        if (gm < M) aptr = A + (size_t)gm * Kreal;
    }
    const int brow  = tid >> 3;
    const int bcolg = (tid & 7) << 3;

    float acc[2][4][4];
#pragma unroll
    for (int i = 0; i < 2; i++)
#pragma unroll
        for (int j = 0; j < 4; j++)
#pragma unroll
            for (int l = 0; l < 4; l++) acc[i][j][l] = 0.f;

    for (int k0 = 0; k0 < Kpad; k0 += 32) {
        float4 f[4];
        if (aptr && (k0 + acolg) < Kreal) {
            const float4* p = (const float4*)(aptr + k0 + acolg);
            f[0] = p[0]; f[1] = p[1]; f[2] = p[2]; f[3] = p[3];
        } else {
            f[0] = f[1] = f[2] = f[3] = make_float4(0.f, 0.f, 0.f, 0.f);
        }
        float* fv = (float*)f;
        if (reluA) {
#pragma unroll
            for (int j = 0; j < 16; j++) fv[j] = fmaxf(fv[j], 0.f);
        }
#pragma unroll
        for (int j = 0; j < 8; j++) {
            __nv_bfloat16 h0, l0, h1, l1;
            split1(fv[2 * j], &h0, &l0);
            split1(fv[2 * j + 1], &h1, &l1);
            __nv_bfloat162 hp; hp.x = h0; hp.y = h1;
            __nv_bfloat162 lp; lp.x = l0; lp.y = l1;
            *(__nv_bfloat162*)&Ah[arow][acolg + 2 * j] = hp;
            *(__nv_bfloat162*)&Al[arow][acolg + 2 * j] = lp;
        }
        {
            size_t off = (size_t)(k0 + brow) * N + n0 + bcolg;
            uint4 vh = *(const uint4*)(Bhg + off);
            uint4 vl = *(const uint4*)(Blg + off);
            *(uint4*)&Bhs[brow][bcolg] = vh;
            *(uint4*)&Bls[brow][bcolg] = vl;
        }
        __syncthreads();

#pragma unroll
        for (int ks = 0; ks < 2; ks++) {
            const int kk = ks << 4;
            uint32_t afh[2][4], afl[2][4];
#pragma unroll
            for (int mt = 0; mt < 2; mt++) {
                const int r = wm * 32 + mt * 16 + (lane & 15);
                const int c = kk + ((lane >> 4) << 3);
                ldsm4(afh[mt], &Ah[r][c]);
                ldsm4(afl[mt], &Al[r][c]);
            }
            uint32_t bfh[2][4], bfl[2][4];
#pragma unroll
            for (int nc = 0; nc < 2; nc++) {
                const int r = kk + (lane & 15);
                const int c = wn * 32 + nc * 16 + ((lane >> 4) << 3);
                ldsm4t(bfh[nc], &Bhs[r][c]);
                ldsm4t(bfl[nc], &Bls[r][c]);
            }
#pragma unroll
            for (int mt = 0; mt < 2; mt++)
#pragma unroll
                for (int nt = 0; nt < 4; nt++) {
                    const int nc = nt >> 1, p = (nt & 1) << 1;
                    uint32_t bh2[2] = { bfh[nc][p], bfh[nc][p + 1] };
                    uint32_t bl2[2] = { bfl[nc][p], bfl[nc][p + 1] };
                    mma16816(acc[mt][nt], afh[mt], bh2);
                    mma16816(acc[mt][nt], afl[mt], bh2);
                    mma16816(acc[mt][nt], afh[mt], bl2);
                }
        }
        __syncthreads();
    }

#pragma unroll
    for (int mt = 0; mt < 2; mt++)
#pragma unroll
        for (int nt = 0; nt < 4; nt++) {
            const int col = n0 + wn * 32 + nt * 8 + ((lane & 3) << 1);
            const float bx = bias[col], by = bias[col + 1];
            const int r0 = m0 + wm * 32 + mt * 16 + (lane >> 2);
            float o0 = acc[mt][nt][0] + bx, o1 = acc[mt][nt][1] + by;
            float o2 = acc[mt][nt][2] + bx, o3 = acc[mt][nt][3] + by;
            if (relu) {
                o0 = fmaxf(o0, 0.f); o1 = fmaxf(o1, 0.f);
                o2 = fmaxf(o2, 0.f); o3 = fmaxf(o3, 0.f);
            }
            if (r0 < M)     { float2 v = make_float2(o0, o1); *(float2*)(C + (size_t)r0 * N + col) = v; }
            if (r0 + 8 < M) { float2 v = make_float2(o2, o3); *(float2*)(C + (size_t)(r0 + 8) * N + col) = v; }
        }
}

/* ------------------------------------------------------------------ */
/* Edge pass (all types): ex = exp(dot(q[dst],k[src])*scale);          */
/* denom[dst] += ex;  S[dst] += ex * v[src]                            */
/* ------------------------------------------------------------------ */
__global__ void edge_fused_all(const float* __restrict__ qkvs,
                               const int* __restrict__ e_src, const int* __restrict__ e_dst,
                               float* __restrict__ S, float* __restrict__ denom) {
    long long w = ((long long)blockIdx.x * blockDim.x + threadIdx.x) >> 5;
    int lane = threadIdx.x & 31;
    if (w >= (long long)T * N_TX) return;
    int t = (int)(w / N_TX);
    int e = (int)(w - (long long)t * N_TX);
    int dd = e_dst[(size_t)t * N_TX + e];
    int ss = e_src[(size_t)t * N_TX + e];
    const float* qk = qkvs + (size_t)t * N_ENT * QLD;
    float4 qv = ((const float4*)(qk + (size_t)dd * QLD))[lane];
    float4 kv = ((const float4*)(qk + (size_t)ss * QLD + 128))[lane];
    float acc = qv.x * kv.x + qv.y * kv.y + qv.z * kv.z + qv.w * kv.w;
#pragma unroll
    for (int o = 16; o; o >>= 1) acc += __shfl_xor_sync(0xFFFFFFFFu, acc, o);
    float exv = expf(acc * SCALE);   /* |score| << 1: no max-shift needed */
    float4 vv = ((const float4*)(qk + (size_t)ss * QLD + 256))[lane];
    float* so = S + ((size_t)t * N_ENT + dd) * D + (lane << 2);
    atomicAdd(so + 0, exv * vv.x);
    atomicAdd(so + 1, exv * vv.y);
    atomicAdd(so + 2, exv * vv.z);
    atomicAdd(so + 3, exv * vv.w);
    if (lane == 0) atomicAdd(&denom[(size_t)t * N_ENT + dd], exv);
}

/* ------------------------------------------------------------------ */
/* Per-node: hn = LN(skip + S/denom), emitted as bf16 hi/lo into Ah/Al */
/* ------------------------------------------------------------------ */
__global__ void norm_ln_all(const float* __restrict__ qkvs,
                            const float* __restrict__ S, const float* __restrict__ denom,
                            const float* __restrict__ ln_g, const float* __restrict__ ln_b,
                            __nv_bfloat16* __restrict__ Hh, __nv_bfloat16* __restrict__ Hl) {
    long long w = ((long long)blockIdx.x * blockDim.x + threadIdx.x) >> 5;
    int lane = threadIdx.x & 31;
    if (w >= (long long)T * N_ENT) return;
    int t = (int)(w / N_ENT);
    int n = (int)(w - (long long)t * N_ENT);
    long long node = w;

    float4 skip = ((const float4*)(qkvs + (size_t)node * QLD + 384))[lane];
    float dn = denom[node];
    float inv = (dn > 0.f) ? (1.f / dn) : 0.f;
    float4 sv = ((const float4*)(S + (size_t)node * D))[lane];
    float x0 = skip.x + sv.x * inv;
    float x1 = skip.y + sv.y * inv;
    float x2 = skip.z + sv.z * inv;
    float x3 = skip.w + sv.w * inv;

    float s = x0 + x1 + x2 + x3;
#pragma unroll
    for (int o = 16; o; o >>= 1) s += __shfl_xor_sync(0xFFFFFFFFu, s, o);
    float mu = s * (1.f / 128.f);
    float d0 = x0 - mu, d1 = x1 - mu, d2 = x2 - mu, d3 = x3 - mu;
    float v = d0 * d0 + d1 * d1 + d2 * d2 + d3 * d3;
#pragma unroll
    for (int o = 16; o; o >>= 1) v += __shfl_xor_sync(0xFFFFFFFFu, v, o);
    float rstd = rsqrtf(v * (1.f / 128.f) + EPS);

    float4 gg = ((const float4*)(ln_g + t * D))[lane];
    float4 bb = ((const float4*)(ln_b + t * D))[lane];
    float hv[4];
    hv[0] = d0 * rstd * gg.x + bb.x;
    hv[1] = d1 * rstd * gg.y + bb.y;
    hv[2] = d2 * rstd * gg.z + bb.z;
    hv[3] = d3 * rstd * gg.w + bb.w;
    __nv_bfloat16 h[4], l[4];
#pragma unroll
    for (int j = 0; j < 4; j++) split1(hv[j], &h[j], &l[j]);
    size_t o = ((size_t)t * MPAD_E + n) * D + (lane << 2);
    *(uint2*)(Hh + o) = *(uint2*)h;
    *(uint2*)(Hl + o) = *(uint2*)l;
}

/* per edge: x1[dst, 0:128] += Y_t[src]  (x1 is 20 MB: L2-resident)    */
__global__ void scatter_all(const float* __restrict__ Y,
                            const int* __restrict__ e_src, const int* __restrict__ e_dst,
                            float* __restrict__ x1) {
    long long w = ((long long)blockIdx.x * blockDim.x + threadIdx.x) >> 5;
    int lane = threadIdx.x & 31;
    if (w >= (long long)T * N_TX) return;
    int t = (int)(w / N_TX);
    int e = (int)(w - (long long)t * N_TX);
    int ss = e_src[(size_t)t * N_TX + e];
    int dd = e_dst[(size_t)t * N_TX + e];
    float4 hv = ((const float4*)(Y + ((size_t)t * MPAD_E + ss) * D))[lane];
    float* c = x1 + (size_t)dd * D + (lane << 2);
    atomicAdd(c + 0, hv.x);
    atomicAdd(c + 1, hv.y);
    atomicAdd(c + 2, hv.z);
    atomicAdd(c + 3, hv.w);
}

__global__ void final_dot(const float* __restrict__ x2, const float* __restrict__ W3,
                          const float* __restrict__ b3, float* __restrict__ out) {
    int r = (blockIdx.x * blockDim.x + threadIdx.x) >> 5;
    int lane = threadIdx.x & 31;
    if (r >= N_TX) return;
    float2 xv = ((const float2*)(x2 + (size_t)r * 64))[lane];
    float2 wv = ((const float2*)W3)[lane];
    float s = xv.x * wv.x + xv.y * wv.y;
#pragma unroll
    for (int o = 16; o; o >>= 1) s += __shfl_xor_sync(0xFFFFFFFFu, s, o);
    if (lane == 0) out[r] = s + b3[0];
}

/* ------------------------------------------------------------------ */
extern "C" void kernel_launch(void* const* d_in, const int* in_sizes, int n_in,
                              void* d_out, int out_size) {
    const float* tx_x  = (const float*)d_in[0];
    const int*   ent_x = (const int*)d_in[1];
    const int*   e_src = (const int*)d_in[2];
    const int*   e_dst = (const int*)d_in[3];
    const float* emb   = (const float*)d_in[4];
    const float* ln_g  = (const float*)d_in[5];
    const float* ln_b  = (const float*)d_in[6];
    const float* Wq = (const float*)d_in[7];  const float* bq = (const float*)d_in[8];
    const float* Wk = (const float*)d_in[9];  const float* bk = (const float*)d_in[10];
    const float* Wv = (const float*)d_in[11]; const float* bv = (const float*)d_in[12];
    const float* Ws = (const float*)d_in[13]; const float* bs = (const float*)d_in[14];
    const float* W1 = (const float*)d_in[15]; const float* b1 = (const float*)d_in[16];
    const float* W2 = (const float*)d_in[17]; const float* b2 = (const float*)d_in[18];
    const float* W3 = (const float*)d_in[19]; const float* b3 = (const float*)d_in[20];
    float* out = (float*)d_out;

    float *qkvs, *S, *denom, *x1, *x2, *bcat, *zero128;
    __nv_bfloat16 *Ah, *Al, *Bh, *Bl, *W1h, *W1l, *W2h, *W2l;
    cudaGetSymbolAddress((void**)&qkvs,   g_qkvs);
    cudaGetSymbolAddress((void**)&S,      g_S);
    cudaGetSymbolAddress((void**)&denom,  g_denom);
    cudaGetSymbolAddress((void**)&x1,     g_x1);
    cudaGetSymbolAddress((void**)&x2,     g_x2);
    cudaGetSymbolAddress((void**)&bcat,   g_bcat);
    cudaGetSymbolAddress((void**)&zero128, g_zero128);
    cudaGetSymbolAddress((void**)&Ah,     g_Ah);
    cudaGetSymbolAddress((void**)&Al,     g_Al);
    cudaGetSymbolAddress((void**)&Bh,     g_Bh);
    cudaGetSymbolAddress((void**)&Bl,     g_Bl);
    cudaGetSymbolAddress((void**)&W1h,    g_W1h);
    cudaGetSymbolAddress((void**)&W1l,    g_W1l);
    cudaGetSymbolAddress((void**)&W2h,    g_W2h);
    cudaGetSymbolAddress((void**)&W2l,    g_W2l);

    const int PREP_TOT = D * QLD + K1PAD * D + D * 64;

    /* 0 */ prep_w<<<(PREP_TOT + 255) / 256, 256>>>(Wq, Wk, Wv, Ws, bq, bk, bv, bs,
                                                    W1, W2, Bh, Bl, bcat, W1h, W1l, W2h, W2l);
    /* 1 */ gather_split_all<<<(int)(((long long)T * N_ENT * 32 + 255) / 256), 256>>>(emb, ent_x, Ah, Al);
    /* 2 */ zero_sd<<<(int)(((long long)T * N_ENT * D / 4 + 255) / 256), 256>>>(S, denom);
    /* 3: x1 = b1 + tx @ W1[0:432]  (rows padded to MPAD_T) */
    gemm128<0><<<dim3(1, MPAD_T / 128, 1), 512>>>(
        tx_x, NULL, NULL, W1h, W1l, b1, x1, N_TX, D, F, KTXPAD, 0, 0, 0, 0);
    /* 4: batched q|k|v|skip GEMM */
    gemm128<1><<<dim3(QLD / 128, MPAD_E / 128, T), 512>>>(
        NULL, Ah, Al, Bh, Bl, bcat, qkvs, N_ENT, QLD, D, D, 0,
        (long long)MPAD_E * D, 0, (long long)N_ENT * QLD);
    /* 5: edge pass */
    {
        long long nwE = (long long)T * N_TX * 32;
        edge_fused_all<<<(int)((nwE + 255) / 256), 256>>>(qkvs, e_src, e_dst, S, denom);
    }
    /* 6: per-node normalize + LN -> bf16 hn into Ah/Al (reuse) */
    {
        long long nwN = (long long)T * N_ENT * 32;
        norm_ln_all<<<(int)((nwN + 255) / 256), 256>>>(qkvs, S, denom, ln_g, ln_b, Ah, Al);
    }
    /* 7: Y_t = hn_t @ W1_t   (Y reuses qkvs buffer; B slice per z) */
    gemm128<1><<<dim3(1, MPAD_E / 128, T), 512>>>(
        NULL, Ah, Al, W1h + (size_t)F * D, W1l + (size_t)F * D, zero128, qkvs,
        N_ENT, D, D, D, 0,
        (long long)MPAD_E * D, (long long)D * D, (long long)MPAD_E * D);
    /* 8: x1[dst] += Y[src] */
    {
        long long nwE = (long long)T * N_TX * 32;
        scatter_all<<<(int)((nwE + 255) / 256), 256>>>(qkvs, e_src, e_dst, x1);
    }
    /* 9: x2 = relu(relu(x1) @ W2 + b2)  (ReLU on A load) */
    gemm_bf16x2<<<dim3(1, (N_TX + 127) / 128), 256>>>(
        x1, W2h, W2l, b2, x2, N_TX, 64, D, D, 1, 1);
    /* 10 */ final_dot<<<(N_TX * 32 + 255) / 256, 256>>>(x2, W3, b3, out);
}

// round 13
// speedup vs baseline: 1.1427x; 1.0293x over previous
#include <cuda_runtime.h>
#include <cuda_bf16.h>
#include <math.h>
#include <stdint.h>
#include <stddef.h>

#define N_ENT 50000
#define N_TX  40000
#define D     128
#define F     432
#define T     11
#define CDIM  (F + T * D)      /* 1840 */
#define K1PAD 1856
#define KTXPAD 448             /* 432 padded */
#define QLD   512
#define EPS   1e-5f
#define SCALE 0.08838834764831845f

#define MPAD_E 50048           /* 391*128 */
#define MPAD_T 40064           /* 313*128 */

/* ------------------------------------------------------------------ */
__device__ float    g_qkvs[(size_t)T * N_ENT * QLD];   /* q|k|v|skip; later reused for Y */
__device__ float    g_S[(size_t)T * N_ENT * D];        /* unnormalized agg */
__device__ float    g_denom[(size_t)T * N_ENT];
__device__ float    g_x1[(size_t)MPAD_T * D];          /* b1 + tx@W1a + scatter(Y) */
__device__ float    g_x2[(size_t)N_TX * 64];
__device__ float    g_bcat[QLD];
__device__ float    g_zero128[D];                      /* stays 0 */
__device__ __nv_bfloat16 g_Ah[(size_t)T * MPAD_E * D], g_Al[(size_t)T * MPAD_E * D];
__device__ __nv_bfloat16 g_Bh[D * QLD],    g_Bl[D * QLD];
__device__ __nv_bfloat16 g_W1h[K1PAD * D], g_W1l[K1PAD * D];
__device__ __nv_bfloat16 g_W2h[D * 64],    g_W2l[D * 64];

/* ------------------------------------------------------------------ */
__device__ __forceinline__ void split1(float v, __nv_bfloat16* h, __nv_bfloat16* l) {
    __nv_bfloat16 hh = __float2bfloat16_rn(v);
    *h = hh;
    *l = __float2bfloat16_rn(v - __bfloat162float(hh));
}

/* One prologue kernel: pack+split qkv weights, split W1, split W2.    */
__global__ void prep_w(const float* __restrict__ Wq, const float* __restrict__ Wk,
                       const float* __restrict__ Wv, const float* __restrict__ Ws,
                       const float* __restrict__ bq, const float* __restrict__ bk,
                       const float* __restrict__ bv, const float* __restrict__ bs,
                       const float* __restrict__ W1, const float* __restrict__ W2,
                       __nv_bfloat16* __restrict__ Bh, __nv_bfloat16* __restrict__ Bl,
                       float* __restrict__ bcat,
                       __nv_bfloat16* __restrict__ W1h, __nv_bfloat16* __restrict__ W1l,
                       __nv_bfloat16* __restrict__ W2h, __nv_bfloat16* __restrict__ W2l) {
    int i = blockIdx.x * blockDim.x + threadIdx.x;
    const int R1 = D * QLD;              /* 65536  */
    const int R2 = R1 + K1PAD * D;       /* +237568 */
    const int R3 = R2 + D * 64;          /* +8192  */
    if (i < R1) {
        int n = i & (QLD - 1);
        int k = i >> 9;
        const float* W = (n < 128) ? Wq : (n < 256) ? Wk : (n < 384) ? Wv : Ws;
        int nn = n & 127;
        split1(W[k * 128 + nn], &Bh[i], &Bl[i]);
        if (k == 0) {
            const float* bb = (n < 128) ? bq : (n < 256) ? bk : (n < 384) ? bv : bs;
            bcat[n] = bb[nn];
        }
    } else if (i < R2) {
        int j = i - R1;
        int k = j >> 7;
        float v = (k < CDIM) ? W1[j] : 0.f;
        split1(v, &W1h[j], &W1l[j]);
    } else if (i < R3) {
        int j = i - R2;
        split1(W2[j], &W2h[j], &W2l[j]);
    }
}

__global__ void gather_split_all(const float* __restrict__ emb, const int* __restrict__ ent_x,
                                 __nv_bfloat16* __restrict__ Ah, __nv_bfloat16* __restrict__ Al) {
    long long i = (long long)blockIdx.x * blockDim.x + threadIdx.x;
    const long long TOT = (long long)T * N_ENT * (D / 4);
    if (i >= TOT) return;
    int c4  = (int)(i & 31);
    long long rowg = i >> 5;
    int t   = (int)(rowg / N_ENT);
    int row = (int)(rowg - (long long)t * N_ENT);
    int r = ent_x[rowg];
    float4 v = ((const float4*)(emb + ((size_t)t * N_ENT + r) * D))[c4];
    float vv[4] = { v.x, v.y, v.z, v.w };
    __nv_bfloat16 h[4], l[4];
#pragma unroll
    for (int j = 0; j < 4; j++) split1(vv[j], &h[j], &l[j]);
    size_t o = ((size_t)t * MPAD_E + row) * D + (c4 << 2);
    *(uint2*)(Ah + o) = *(uint2*)h;
    *(uint2*)(Al + o) = *(uint2*)l;
}

__global__ void zero_sd(float* __restrict__ S, float* __restrict__ denom) {
    long long i = (long long)blockIdx.x * blockDim.x + threadIdx.x;
    const long long S4 = (long long)T * N_ENT * D / 4;
    if (i < S4) ((float4*)S)[i] = make_float4(0.f, 0.f, 0.f, 0.f);
    if (i < (long long)T * N_ENT) denom[i] = 0.f;
}

/* ------------------------------------------------------------------ */
__device__ __forceinline__ void ldsm4(uint32_t* r, const void* p) {
    uint32_t a = (uint32_t)__cvta_generic_to_shared(p);
    asm volatile("ldmatrix.sync.aligned.m8n8.x4.shared.b16 {%0,%1,%2,%3}, [%4];"
                 : "=r"(r[0]), "=r"(r[1]), "=r"(r[2]), "=r"(r[3]) : "r"(a));
}
__device__ __forceinline__ void ldsm4t(uint32_t* r, const void* p) {
    uint32_t a = (uint32_t)__cvta_generic_to_shared(p);
    asm volatile("ldmatrix.sync.aligned.m8n8.x4.trans.shared.b16 {%0,%1,%2,%3}, [%4];"
                 : "=r"(r[0]), "=r"(r[1]), "=r"(r[2]), "=r"(r[3]) : "r"(a));
}
__device__ __forceinline__ void mma16816(float* c, const uint32_t* a, const uint32_t* b) {
    asm volatile(
        "mma.sync.aligned.m16n8k16.row.col.f32.bf16.bf16.f32 "
        "{%0,%1,%2,%3}, {%4,%5,%6,%7}, {%8,%9}, {%0,%1,%2,%3};\n"
        : "+f"(c[0]), "+f"(c[1]), "+f"(c[2]), "+f"(c[3])
        : "r"(a[0]), "r"(a[1]), "r"(a[2]), "r"(a[3]), "r"(b[0]), "r"(b[1]));
}

/* ------------------------------------------------------------------ */
/* gemm128 batched, 512 threads, DOUBLE-BUFFERED SMEM (dynamic).       */
/* BM=BN=128 BK=32, 16 warps 4x4, warp tile 32x32.                     */
/* One __syncthreads per k-iter; SMEM stores overlap MMA.              */
/* ------------------------------------------------------------------ */
#define ASTR  40
#define BSTR2 136
#define A_ELE (128 * ASTR)                 /* 5120 bf16 per A buffer   */
#define B_ELE (32 * BSTR2)                 /* 4352 bf16 per B buffer   */
#define STAGE_ELE (2 * A_ELE + 2 * B_ELE)  /* Ah|Al|Bh|Bl per stage    */
#define GEMM_SMEM_BYTES (2 * STAGE_ELE * 2)/* 75776 bytes              */

template<int SPLITA>
__global__ void __launch_bounds__(512) gemm128(
    const float* __restrict__ Afp,
    const __nv_bfloat16* __restrict__ Ahg, const __nv_bfloat16* __restrict__ Alg,
    const __nv_bfloat16* __restrict__ Bhg, const __nv_bfloat16* __restrict__ Blg,
    const float* __restrict__ bias, float* __restrict__ C,
    int M, int N, int Kreal, int Kpad, int relu,
    long long strideA, long long strideB, long long strideC)
{
    extern __shared__ __nv_bfloat16 sm[];

    const int tid  = threadIdx.x;
    const int lane = tid & 31;
    const int warp = tid >> 5;          /* 0..15 */
    const int wm   = warp >> 2;         /* 0..3  */
    const int wn   = warp & 3;          /* 0..3  */
    const int m0   = blockIdx.y * 128;
    const int n0   = blockIdx.x * 128;
    const long long zA = (long long)blockIdx.z * strideA;
    const long long zB = (long long)blockIdx.z * strideB;
    const long long zC = (long long)blockIdx.z * strideC;

    const int arow  = tid >> 2;          /* 0..127 */
    const int acolg = (tid & 3) << 3;    /* 0,8,16,24 */
    const int brow  = tid >> 4;          /* 0..31  */
    const int bcolg = (tid & 15) << 3;   /* 0..120 */

    const float* afprow = NULL;
    if (!SPLITA && (m0 + arow) < M) afprow = Afp + (size_t)(m0 + arow) * Kreal;

    float acc[2][4][4];
#pragma unroll
    for (int a = 0; a < 2; a++)
#pragma unroll
        for (int b = 0; b < 4; b++)
#pragma unroll
            for (int c = 0; c < 4; c++) acc[a][b][c] = 0.f;

    uint4  sAh, sAl;
    float4 sAf[2];
    uint4  sBh, sBl;

#define LOADT(K0)                                                              \
    do {                                                                       \
        if (SPLITA) {                                                          \
            size_t ao = (size_t)(zA + (long long)(m0 + arow) * Kreal           \
                                 + (K0) + acolg);                              \
            sAh = *(const uint4*)(Ahg + ao);                                   \
            sAl = *(const uint4*)(Alg + ao);                                   \
        } else {                                                               \
            if (afprow && (K0) + acolg < Kreal) {                              \
                const float4* p = (const float4*)(afprow + (K0) + acolg);      \
                sAf[0] = p[0]; sAf[1] = p[1];                                  \
            } else {                                                           \
                sAf[0] = sAf[1] = make_float4(0.f, 0.f, 0.f, 0.f);             \
            }                                                                  \
        }                                                                      \
        size_t bo = (size_t)(zB + (long long)((K0) + brow) * N + n0 + bcolg);  \
        sBh = *(const uint4*)(Bhg + bo);                                       \
        sBl = *(const uint4*)(Blg + bo);                                       \
    } while (0)

#define STORET(S)                                                              \
    do {                                                                       \
        __nv_bfloat16* dAh = sm + (S) * STAGE_ELE;                             \
        __nv_bfloat16* dAl = dAh + A_ELE;                                      \
        __nv_bfloat16* dBh = dAl + A_ELE;                                      \
        __nv_bfloat16* dBl = dBh + B_ELE;                                      \
        if (SPLITA) {                                                          \
            *(uint4*)(dAh + arow * ASTR + acolg) = sAh;                        \
            *(uint4*)(dAl + arow * ASTR + acolg) = sAl;                        \
        } else {                                                               \
            const float* fv = (const float*)sAf;                               \
            _Pragma("unroll")                                                  \
            for (int j = 0; j < 4; j++) {                                      \
                __nv_bfloat16 h0, l0, h1, l1;                                  \
                split1(fv[2 * j], &h0, &l0);                                   \
                split1(fv[2 * j + 1], &h1, &l1);                               \
                __nv_bfloat162 hp; hp.x = h0; hp.y = h1;                       \
                __nv_bfloat162 lp; lp.x = l0; lp.y = l1;                       \
                *(__nv_bfloat162*)(dAh + arow * ASTR + acolg + 2 * j) = hp;    \
                *(__nv_bfloat162*)(dAl + arow * ASTR + acolg + 2 * j) = lp;    \
            }                                                                  \
        }                                                                      \
        *(uint4*)(dBh + brow * BSTR2 + bcolg) = sBh;                           \
        *(uint4*)(dBl + brow * BSTR2 + bcolg) = sBl;                           \
    } while (0)

    LOADT(0);
    STORET(0);
    __syncthreads();

    int cur = 0;
    for (int k0 = 0; k0 < Kpad; k0 += 32) {
        int kn = k0 + 32;
        if (kn < Kpad) LOADT(kn);

        const __nv_bfloat16* cAh = sm + cur * STAGE_ELE;
        const __nv_bfloat16* cAl = cAh + A_ELE;
        const __nv_bfloat16* cBh = cAl + A_ELE;
        const __nv_bfloat16* cBl = cBh + B_ELE;

#pragma unroll
        for (int ks = 0; ks < 2; ks++) {
            const int kk = ks << 4;
            uint32_t afh[2][4], afl[2][4];
#pragma unroll
            for (int mt = 0; mt < 2; mt++) {
                const int r = wm * 32 + mt * 16 + (lane & 15);
                const int c = kk + ((lane >> 4) << 3);
                ldsm4(afh[mt], cAh + r * ASTR + c);
                ldsm4(afl[mt], cAl + r * ASTR + c);
            }
            uint32_t bfh[2][4], bfl[2][4];
#pragma unroll
            for (int nc = 0; nc < 2; nc++) {
                const int r = kk + (lane & 15);
                const int c = wn * 32 + nc * 16 + ((lane >> 4) << 3);
                ldsm4t(bfh[nc], cBh + r * BSTR2 + c);
                ldsm4t(bfl[nc], cBl + r * BSTR2 + c);
            }
#pragma unroll
            for (int mt = 0; mt < 2; mt++)
#pragma unroll
                for (int nt = 0; nt < 4; nt++) {
                    const int nc = nt >> 1, p = (nt & 1) << 1;
                    uint32_t bh2[2] = { bfh[nc][p], bfh[nc][p + 1] };
                    uint32_t bl2[2] = { bfl[nc][p], bfl[nc][p + 1] };
                    mma16816(acc[mt][nt], afh[mt], bh2);
                    mma16816(acc[mt][nt], afl[mt], bh2);
                    mma16816(acc[mt][nt], afh[mt], bl2);
                }
        }

        if (kn < Kpad) {
            STORET(1 - cur);
            __syncthreads();
            cur ^= 1;
        }
    }
#undef LOADT
#undef STORET

#pragma unroll
    for (int mt = 0; mt < 2; mt++)
#pragma unroll
        for (int nt = 0; nt < 4; nt++) {
            const int col = n0 + wn * 32 + nt * 8 + ((lane & 3) << 1);
            const float bx = bias[col], by = bias[col + 1];
            const int r0 = m0 + wm * 32 + mt * 16 + (lane >> 2);
            float o0 = acc[mt][nt][0] + bx, o1 = acc[mt][nt][1] + by;
            float o2 = acc[mt][nt][2] + bx, o3 = acc[mt][nt][3] + by;
            if (relu) {
                o0 = fmaxf(o0, 0.f); o1 = fmaxf(o1, 0.f);
                o2 = fmaxf(o2, 0.f); o3 = fmaxf(o3, 0.f);
            }
            if (r0 < M)     { float2 v = make_float2(o0, o1);
                              *(float2*)(C + zC + (size_t)r0 * N + col) = v; }
            if (r0 + 8 < M) { float2 v = make_float2(o2, o3);
                              *(float2*)(C + zC + (size_t)(r0 + 8) * N + col) = v; }
        }
}

/* ------------------------------------------------------------------ */
/* BN=64 GEMM for classifier GEMM2 (N=64); optional ReLU on A load.    */
/* ------------------------------------------------------------------ */
#define BSTR 72
__global__ void __launch_bounds__(256) gemm_bf16x2(
    const float* __restrict__ A,
    const __nv_bfloat16* __restrict__ Bhg, const __nv_bfloat16* __restrict__ Blg,
    const float* __restrict__ bias, float* __restrict__ C,
    int M, int N, int Kreal, int Kpad, int relu, int reluA)
{
    __shared__ __nv_bfloat16 Ah[128][ASTR];
    __shared__ __nv_bfloat16 Al[128][ASTR];
    __shared__ __nv_bfloat16 Bhs[32][BSTR];
    __shared__ __nv_bfloat16 Bls[32][BSTR];

    const int tid  = threadIdx.x;
    const int lane = tid & 31;
    const int warp = tid >> 5;
    const int wm   = warp >> 1;
    const int wn   = warp & 1;
    const int m0   = blockIdx.y * 128;
    const int n0   = blockIdx.x * 64;

    const int arow  = tid >> 1;
    const int acolg = (tid & 1) << 4;
    const float* aptr = NULL;
    {
        int gm = m0 + arow;
        if (gm < M) aptr = A + (size_t)gm * Kreal;
    }
    const int brow  = tid >> 3;
    const int bcolg = (tid & 7) << 3;

    float acc[2][4][4];
#pragma unroll
    for (int i = 0; i < 2; i++)
#pragma unroll
        for (int j = 0; j < 4; j++)
#pragma unroll
            for (int l = 0; l < 4; l++) acc[i][j][l] = 0.f;

    for (int k0 = 0; k0 < Kpad; k0 += 32) {
        float4 f[4];
        if (aptr && (k0 + acolg) < Kreal) {
            const float4* p = (const float4*)(aptr + k0 + acolg);
            f[0] = p[0]; f[1] = p[1]; f[2] = p[2]; f[3] = p[3];
        } else {
            f[0] = f[1] = f[2] = f[3] = make_float4(0.f, 0.f, 0.f, 0.f);
        }
        float* fv = (float*)f;
        if (reluA) {
#pragma unroll
            for (int j = 0; j < 16; j++) fv[j] = fmaxf(fv[j], 0.f);
        }
#pragma unroll
        for (int j = 0; j < 8; j++) {
            __nv_bfloat16 h0, l0, h1, l1;
            split1(fv[2 * j], &h0, &l0);
            split1(fv[2 * j + 1], &h1, &l1);
            __nv_bfloat162 hp; hp.x = h0; hp.y = h1;
            __nv_bfloat162 lp; lp.x = l0; lp.y = l1;
            *(__nv_bfloat162*)&Ah[arow][acolg + 2 * j] = hp;
            *(__nv_bfloat162*)&Al[arow][acolg + 2 * j] = lp;
        }
        {
            size_t off = (size_t)(k0 + brow) * N + n0 + bcolg;
            uint4 vh = *(const uint4*)(Bhg + off);
            uint4 vl = *(const uint4*)(Blg + off);
            *(uint4*)&Bhs[brow][bcolg] = vh;
            *(uint4*)&Bls[brow][bcolg] = vl;
        }
        __syncthreads();

#pragma unroll
        for (int ks = 0; ks < 2; ks++) {
            const int kk = ks << 4;
            uint32_t afh[2][4], afl[2][4];
#pragma unroll
            for (int mt = 0; mt < 2; mt++) {
                const int r = wm * 32 + mt * 16 + (lane & 15);
                const int c = kk + ((lane >> 4) << 3);
                ldsm4(afh[mt], &Ah[r][c]);
                ldsm4(afl[mt], &Al[r][c]);
            }
            uint32_t bfh[2][4], bfl[2][4];
#pragma unroll
            for (int nc = 0; nc < 2; nc++) {
                const int r = kk + (lane & 15);
                const int c = wn * 32 + nc * 16 + ((lane >> 4) << 3);
                ldsm4t(bfh[nc], &Bhs[r][c]);
                ldsm4t(bfl[nc], &Bls[r][c]);
            }
#pragma unroll
            for (int mt = 0; mt < 2; mt++)
#pragma unroll
                for (int nt = 0; nt < 4; nt++) {
                    const int nc = nt >> 1, p = (nt & 1) << 1;
                    uint32_t bh2[2] = { bfh[nc][p], bfh[nc][p + 1] };
                    uint32_t bl2[2] = { bfl[nc][p], bfl[nc][p + 1] };
                    mma16816(acc[mt][nt], afh[mt], bh2);
                    mma16816(acc[mt][nt], afl[mt], bh2);
                    mma16816(acc[mt][nt], afh[mt], bl2);
                }
        }
        __syncthreads();
    }

#pragma unroll
    for (int mt = 0; mt < 2; mt++)
#pragma unroll
        for (int nt = 0; nt < 4; nt++) {
            const int col = n0 + wn * 32 + nt * 8 + ((lane & 3) << 1);
            const float bx = bias[col], by = bias[col + 1];
            const int r0 = m0 + wm * 32 + mt * 16 + (lane >> 2);
            float o0 = acc[mt][nt][0] + bx, o1 = acc[mt][nt][1] + by;
            float o2 = acc[mt][nt][2] + bx, o3 = acc[mt][nt][3] + by;
            if (relu) {
                o0 = fmaxf(o0, 0.f); o1 = fmaxf(o1, 0.f);
                o2 = fmaxf(o2, 0.f); o3 = fmaxf(o3, 0.f);
            }
            if (r0 < M)     { float2 v = make_float2(o0, o1); *(float2*)(C + (size_t)r0 * N + col) = v; }
            if (r0 + 8 < M) { float2 v = make_float2(o2, o3); *(float2*)(C + (size_t)(r0 + 8) * N + col) = v; }
        }
}

/* ------------------------------------------------------------------ */
/* Edge pass (all types): ex = exp(dot(q[dst],k[src])*scale);          */
/* denom[dst] += ex;  S[dst] += ex * v[src]                            */
/* ------------------------------------------------------------------ */
__global__ void edge_fused_all(const float* __restrict__ qkvs,
                               const int* __restrict__ e_src, const int* __restrict__ e_dst,
                               float* __restrict__ S, float* __restrict__ denom) {
    long long w = ((long long)blockIdx.x * blockDim.x + threadIdx.x) >> 5;
    int lane = threadIdx.x & 31;
    if (w >= (long long)T * N_TX) return;
    int t = (int)(w / N_TX);
    int e = (int)(w - (long long)t * N_TX);
    int dd = e_dst[(size_t)t * N_TX + e];
    int ss = e_src[(size_t)t * N_TX + e];
    const float* qk = qkvs + (size_t)t * N_ENT * QLD;
    float4 qv = ((const float4*)(qk + (size_t)dd * QLD))[lane];
    float4 kv = ((const float4*)(qk + (size_t)ss * QLD + 128))[lane];
    float acc = qv.x * kv.x + qv.y * kv.y + qv.z * kv.z + qv.w * kv.w;
#pragma unroll
    for (int o = 16; o; o >>= 1) acc += __shfl_xor_sync(0xFFFFFFFFu, acc, o);
    float exv = expf(acc * SCALE);   /* |score| << 1: no max-shift needed */
    float4 vv = ((const float4*)(qk + (size_t)ss * QLD + 256))[lane];
    float* so = S + ((size_t)t * N_ENT + dd) * D + (lane << 2);
    atomicAdd(so + 0, exv * vv.x);
    atomicAdd(so + 1, exv * vv.y);
    atomicAdd(so + 2, exv * vv.z);
    atomicAdd(so + 3, exv * vv.w);
    if (lane == 0) atomicAdd(&denom[(size_t)t * N_ENT + dd], exv);
}

/* ------------------------------------------------------------------ */
/* Per-node: hn = LN(skip + S/denom), emitted as bf16 hi/lo into Ah/Al */
/* ------------------------------------------------------------------ */
__global__ void norm_ln_all(const float* __restrict__ qkvs,
                            const float* __restrict__ S, const float* __restrict__ denom,
                            const float* __restrict__ ln_g, const float* __restrict__ ln_b,
                            __nv_bfloat16* __restrict__ Hh, __nv_bfloat16* __restrict__ Hl) {
    long long w = ((long long)blockIdx.x * blockDim.x + threadIdx.x) >> 5;
    int lane = threadIdx.x & 31;
    if (w >= (long long)T * N_ENT) return;
    int t = (int)(w / N_ENT);
    int n = (int)(w - (long long)t * N_ENT);
    long long node = w;

    float4 skip = ((const float4*)(qkvs + (size_t)node * QLD + 384))[lane];
    float dn = denom[node];
    float inv = (dn > 0.f) ? (1.f / dn) : 0.f;
    float4 sv = ((const float4*)(S + (size_t)node * D))[lane];
    float x0 = skip.x + sv.x * inv;
    float x1 = skip.y + sv.y * inv;
    float x2 = skip.z + sv.z * inv;
    float x3 = skip.w + sv.w * inv;

    float s = x0 + x1 + x2 + x3;
#pragma unroll
    for (int o = 16; o; o >>= 1) s += __shfl_xor_sync(0xFFFFFFFFu, s, o);
    float mu = s * (1.f / 128.f);
    float d0 = x0 - mu, d1 = x1 - mu, d2 = x2 - mu, d3 = x3 - mu;
    float v = d0 * d0 + d1 * d1 + d2 * d2 + d3 * d3;
#pragma unroll
    for (int o = 16; o; o >>= 1) v += __shfl_xor_sync(0xFFFFFFFFu, v, o);
    float rstd = rsqrtf(v * (1.f / 128.f) + EPS);

    float4 gg = ((const float4*)(ln_g + t * D))[lane];
    float4 bb = ((const float4*)(ln_b + t * D))[lane];
    float hv[4];
    hv[0] = d0 * rstd * gg.x + bb.x;
    hv[1] = d1 * rstd * gg.y + bb.y;
    hv[2] = d2 * rstd * gg.z + bb.z;
    hv[3] = d3 * rstd * gg.w + bb.w;
    __nv_bfloat16 h[4], l[4];
#pragma unroll
    for (int j = 0; j < 4; j++) split1(hv[j], &h[j], &l[j]);
    size_t o = ((size_t)t * MPAD_E + n) * D + (lane << 2);
    *(uint2*)(Hh + o) = *(uint2*)h;
    *(uint2*)(Hl + o) = *(uint2*)l;
}

/* per edge: x1[dst, 0:128] += Y_t[src]  (x1 is 20 MB: L2-resident)    */
__global__ void scatter_all(const float* __restrict__ Y,
                            const int* __restrict__ e_src, const int* __restrict__ e_dst,
                            float* __restrict__ x1) {
    long long w = ((long long)blockIdx.x * blockDim.x + threadIdx.x) >> 5;
    int lane = threadIdx.x & 31;
    if (w >= (long long)T * N_TX) return;
    int t = (int)(w / N_TX);
    int e = (int)(w - (long long)t * N_TX);
    int ss = e_src[(size_t)t * N_TX + e];
    int dd = e_dst[(size_t)t * N_TX + e];
    float4 hv = ((const float4*)(Y + ((size_t)t * MPAD_E + ss) * D))[lane];
    float* c = x1 + (size_t)dd * D + (lane << 2);
    atomicAdd(c + 0, hv.x);
    atomicAdd(c + 1, hv.y);
    atomicAdd(c + 2, hv.z);
    atomicAdd(c + 3, hv.w);
}

__global__ void final_dot(const float* __restrict__ x2, const float* __restrict__ W3,
                          const float* __restrict__ b3, float* __restrict__ out) {
    int r = (blockIdx.x * blockDim.x + threadIdx.x) >> 5;
    int lane = threadIdx.x & 31;
    if (r >= N_TX) return;
    float2 xv = ((const float2*)(x2 + (size_t)r * 64))[lane];
    float2 wv = ((const float2*)W3)[lane];
    float s = xv.x * wv.x + xv.y * wv.y;
#pragma unroll
    for (int o = 16; o; o >>= 1) s += __shfl_xor_sync(0xFFFFFFFFu, s, o);
    if (lane == 0) out[r] = s + b3[0];
}

/* ------------------------------------------------------------------ */
extern "C" void kernel_launch(void* const* d_in, const int* in_sizes, int n_in,
                              void* d_out, int out_size) {
    const float* tx_x  = (const float*)d_in[0];
    const int*   ent_x = (const int*)d_in[1];
    const int*   e_src = (const int*)d_in[2];
    const int*   e_dst = (const int*)d_in[3];
    const float* emb   = (const float*)d_in[4];
    const float* ln_g  = (const float*)d_in[5];
    const float* ln_b  = (const float*)d_in[6];
    const float* Wq = (const float*)d_in[7];  const float* bq = (const float*)d_in[8];
    const float* Wk = (const float*)d_in[9];  const float* bk = (const float*)d_in[10];
    const float* Wv = (const float*)d_in[11]; const float* bv = (const float*)d_in[12];
    const float* Ws = (const float*)d_in[13]; const float* bs = (const float*)d_in[14];
    const float* W1 = (const float*)d_in[15]; const float* b1 = (const float*)d_in[16];
    const float* W2 = (const float*)d_in[17]; const float* b2 = (const float*)d_in[18];
    const float* W3 = (const float*)d_in[19]; const float* b3 = (const float*)d_in[20];
    float* out = (float*)d_out;

    float *qkvs, *S, *denom, *x1, *x2, *bcat, *zero128;
    __nv_bfloat16 *Ah, *Al, *Bh, *Bl, *W1h, *W1l, *W2h, *W2l;
    cudaGetSymbolAddress((void**)&qkvs,   g_qkvs);
    cudaGetSymbolAddress((void**)&S,      g_S);
    cudaGetSymbolAddress((void**)&denom,  g_denom);
    cudaGetSymbolAddress((void**)&x1,     g_x1);
    cudaGetSymbolAddress((void**)&x2,     g_x2);
    cudaGetSymbolAddress((void**)&bcat,   g_bcat);
    cudaGetSymbolAddress((void**)&zero128, g_zero128);
    cudaGetSymbolAddress((void**)&Ah,     g_Ah);
    cudaGetSymbolAddress((void**)&Al,     g_Al);
    cudaGetSymbolAddress((void**)&Bh,     g_Bh);
    cudaGetSymbolAddress((void**)&Bl,     g_Bl);
    cudaGetSymbolAddress((void**)&W1h,    g_W1h);
    cudaGetSymbolAddress((void**)&W1l,    g_W1l);
    cudaGetSymbolAddress((void**)&W2h,    g_W2h);
    cudaGetSymbolAddress((void**)&W2l,    g_W2l);

    /* enable >48KB dynamic smem for the double-buffered GEMM */
    cudaFuncSetAttribute(gemm128<0>, cudaFuncAttributeMaxDynamicSharedMemorySize, GEMM_SMEM_BYTES);
    cudaFuncSetAttribute(gemm128<1>, cudaFuncAttributeMaxDynamicSharedMemorySize, GEMM_SMEM_BYTES);

    const int PREP_TOT = D * QLD + K1PAD * D + D * 64;

    /* 0 */ prep_w<<<(PREP_TOT + 255) / 256, 256>>>(Wq, Wk, Wv, Ws, bq, bk, bv, bs,
                                                    W1, W2, Bh, Bl, bcat, W1h, W1l, W2h, W2l);
    /* 1 */ gather_split_all<<<(int)(((long long)T * N_ENT * 32 + 255) / 256), 256>>>(emb, ent_x, Ah, Al);
    /* 2 */ zero_sd<<<(int)(((long long)T * N_ENT * D / 4 + 255) / 256), 256>>>(S, denom);
    /* 3: x1 = b1 + tx @ W1[0:432]  (rows padded to MPAD_T) */
    gemm128<0><<<dim3(1, MPAD_T / 128, 1), 512, GEMM_SMEM_BYTES>>>(
        tx_x, NULL, NULL, W1h, W1l, b1, x1, N_TX, D, F, KTXPAD, 0, 0, 0, 0);
    /* 4: batched q|k|v|skip GEMM */
    gemm128<1><<<dim3(QLD / 128, MPAD_E / 128, T), 512, GEMM_SMEM_BYTES>>>(
        NULL, Ah, Al, Bh, Bl, bcat, qkvs, N_ENT, QLD, D, D, 0,
        (long long)MPAD_E * D, 0, (long long)N_ENT * QLD);
    /* 5: edge pass */
    {
        long long nwE = (long long)T * N_TX * 32;
        edge_fused_all<<<(int)((nwE + 255) / 256), 256>>>(qkvs, e_src, e_dst, S, denom);
    }
    /* 6: per-node normalize + LN -> bf16 hn into Ah/Al (reuse) */
    {
        long long nwN = (long long)T * N_ENT * 32;
        norm_ln_all<<<(int)((nwN + 255) / 256), 256>>>(qkvs, S, denom, ln_g, ln_b, Ah, Al);
    }
    /* 7: Y_t = hn_t @ W1_t   (Y reuses qkvs buffer; B slice per z) */
    gemm128<1><<<dim3(1, MPAD_E / 128, T), 512, GEMM_SMEM_BYTES>>>(
        NULL, Ah, Al, W1h + (size_t)F * D, W1l + (size_t)F * D, zero128, qkvs,
        N_ENT, D, D, D, 0,
        (long long)MPAD_E * D, (long long)D * D, (long long)MPAD_E * D);
    /* 8: x1[dst] += Y[src] */
    {
        long long nwE = (long long)T * N_TX * 32;
        scatter_all<<<(int)((nwE + 255) / 256), 256>>>(qkvs, e_src, e_dst, x1);
    }
    /* 9: x2 = relu(relu(x1) @ W2 + b2)  (ReLU on A load) */
    gemm_bf16x2<<<dim3(1, (N_TX + 127) / 128), 256>>>(
        x1, W2h, W2l, b2, x2, N_TX, 64, D, D, 1, 1);
    /* 10 */ final_dot<<<(N_TX * 32 + 255) / 256, 256>>>(x2, W3, b3, out);
}